// round 1
// baseline (speedup 1.0000x reference)
#include <cuda_runtime.h>

// Problem constants
#define BATCH 2
#define SEQ   2048
#define DIM   1024
#define NH    16
#define HD    64
#define MROWS (BATCH * SEQ)   // 4096

// Scratch (allocation-free rule: __device__ globals)
__device__ float g_q[MROWS * DIM];
__device__ float g_k[MROWS * DIM];
__device__ float g_v[MROWS * DIM];
__device__ float g_ao[MROWS * DIM];

// ---------------------------------------------------------------------------
// C[m][n] = sum_k A[m][k] * B[n][k] + bias[n]     (NT GEMM, both K-contiguous)
// 128x128 block tile, BK=8, 256 threads, 8x8 per thread.
// ---------------------------------------------------------------------------
__global__ __launch_bounds__(256) void sgemm_nt_bias(
    const float* __restrict__ A, const float* __restrict__ B,
    const float* __restrict__ bias, float* __restrict__ C,
    int M, int N, int Kd)
{
    __shared__ __align__(16) float As[8][128];
    __shared__ __align__(16) float Bs[8][128];

    const int bm = blockIdx.y * 128;
    const int bn = blockIdx.x * 128;
    const int t  = threadIdx.x;
    const int lrow = t >> 1;          // 0..127
    const int lk   = (t & 1) * 4;     // 0 or 4
    const int ty   = t >> 4;          // 0..15
    const int tx   = t & 15;          // 0..15

    const float* Aptr = A + (size_t)(bm + lrow) * Kd + lk;
    const float* Bptr = B + (size_t)(bn + lrow) * Kd + lk;

    float acc[8][8];
#pragma unroll
    for (int i = 0; i < 8; i++)
#pragma unroll
        for (int j = 0; j < 8; j++) acc[i][j] = 0.f;

    for (int k0 = 0; k0 < Kd; k0 += 8) {
        float4 av = *reinterpret_cast<const float4*>(Aptr + k0);
        float4 bv = *reinterpret_cast<const float4*>(Bptr + k0);
        As[lk + 0][lrow] = av.x; As[lk + 1][lrow] = av.y;
        As[lk + 2][lrow] = av.z; As[lk + 3][lrow] = av.w;
        Bs[lk + 0][lrow] = bv.x; Bs[lk + 1][lrow] = bv.y;
        Bs[lk + 2][lrow] = bv.z; Bs[lk + 3][lrow] = bv.w;
        __syncthreads();

#pragma unroll
        for (int kk = 0; kk < 8; kk++) {
            float4 a0 = *reinterpret_cast<const float4*>(&As[kk][ty * 4]);
            float4 a1 = *reinterpret_cast<const float4*>(&As[kk][ty * 4 + 64]);
            float4 b0 = *reinterpret_cast<const float4*>(&Bs[kk][tx * 4]);
            float4 b1 = *reinterpret_cast<const float4*>(&Bs[kk][tx * 4 + 64]);
            float af[8] = {a0.x, a0.y, a0.z, a0.w, a1.x, a1.y, a1.z, a1.w};
            float bf[8] = {b0.x, b0.y, b0.z, b0.w, b1.x, b1.y, b1.z, b1.w};
#pragma unroll
            for (int i = 0; i < 8; i++)
#pragma unroll
                for (int j = 0; j < 8; j++)
                    acc[i][j] = fmaf(af[i], bf[j], acc[i][j]);
        }
        __syncthreads();
    }

#pragma unroll
    for (int ih = 0; ih < 2; ih++)
#pragma unroll
        for (int i = 0; i < 4; i++) {
            int row = bm + ih * 64 + ty * 4 + i;
#pragma unroll
            for (int jh = 0; jh < 2; jh++) {
                int col = bn + jh * 64 + tx * 4;
                float4 ov;
                ov.x = acc[ih * 4 + i][jh * 4 + 0] + bias[col + 0];
                ov.y = acc[ih * 4 + i][jh * 4 + 1] + bias[col + 1];
                ov.z = acc[ih * 4 + i][jh * 4 + 2] + bias[col + 2];
                ov.w = acc[ih * 4 + i][jh * 4 + 3] + bias[col + 3];
                *reinterpret_cast<float4*>(&C[(size_t)row * N + col]) = ov;
            }
        }
}

// ---------------------------------------------------------------------------
// Causal flash attention, fp32. One block per (m-tile, head, batch).
// BM = BN = 64, DK = 64, 256 threads, 4x4 per thread, online softmax.
// Row groups of 16 threads reduced with width-16 shuffles.
// ---------------------------------------------------------------------------
#define PAD 65
#define ATTN_SMEM (4 * 64 * PAD * (int)sizeof(float))

__global__ __launch_bounds__(256) void attn_kernel(
    const float* __restrict__ q, const float* __restrict__ k,
    const float* __restrict__ v, float* __restrict__ o)
{
    extern __shared__ float sm[];
    float* Qs = sm;                  // [64][PAD]
    float* Ks = sm + 64 * PAD;
    float* Vs = sm + 2 * 64 * PAD;
    float* Ps = sm + 3 * 64 * PAD;

    const int mt = blockIdx.x;       // query tile
    const int h  = blockIdx.y;
    const int b  = blockIdx.z;
    const int t  = threadIdx.x;
    const int tr = t >> 4;           // 0..15 (row group)
    const int tc = t & 15;           // 0..15 (col group)

    const float* qb = q + ((size_t)(b * SEQ + mt * 64)) * DIM + h * HD;
    for (int i = t; i < 64 * 64; i += 256) {
        int r = i >> 6, c = i & 63;
        Qs[r * PAD + c] = qb[(size_t)r * DIM + c];
    }

    float m_i[4], l_i[4], oa[4][4];
#pragma unroll
    for (int i = 0; i < 4; i++) {
        m_i[i] = -1e30f; l_i[i] = 0.f;
#pragma unroll
        for (int j = 0; j < 4; j++) oa[i][j] = 0.f;
    }
    __syncthreads();

    for (int nt = 0; nt <= mt; nt++) {
        const float* kb = k + ((size_t)(b * SEQ + nt * 64)) * DIM + h * HD;
        const float* vb = v + ((size_t)(b * SEQ + nt * 64)) * DIM + h * HD;
        for (int i = t; i < 64 * 64; i += 256) {
            int r = i >> 6, c = i & 63;
            Ks[r * PAD + c] = kb[(size_t)r * DIM + c];
            Vs[r * PAD + c] = vb[(size_t)r * DIM + c];
        }
        __syncthreads();

        // S = Q @ K^T (4x4 per thread)
        float s[4][4] = {};
#pragma unroll 8
        for (int kk = 0; kk < 64; kk++) {
            float a[4], bb[4];
#pragma unroll
            for (int i = 0; i < 4; i++) a[i]  = Qs[(tr * 4 + i) * PAD + kk];
#pragma unroll
            for (int j = 0; j < 4; j++) bb[j] = Ks[(tc * 4 + j) * PAD + kk];
#pragma unroll
            for (int i = 0; i < 4; i++)
#pragma unroll
                for (int j = 0; j < 4; j++)
                    s[i][j] = fmaf(a[i], bb[j], s[i][j]);
        }

        // scale + causal mask (only diagonal tile has masked entries)
#pragma unroll
        for (int i = 0; i < 4; i++)
#pragma unroll
            for (int j = 0; j < 4; j++) {
                s[i][j] *= 0.125f;                       // 1/sqrt(64)
                if (nt == mt && (tc * 4 + j) > (tr * 4 + i)) s[i][j] = -1e9f;
            }

        // online softmax update
        float mn[4], alpha[4], p[4][4], rs[4];
#pragma unroll
        for (int i = 0; i < 4; i++) {
            float rm = fmaxf(fmaxf(s[i][0], s[i][1]), fmaxf(s[i][2], s[i][3]));
#pragma unroll
            for (int off = 8; off > 0; off >>= 1)
                rm = fmaxf(rm, __shfl_xor_sync(0xffffffffu, rm, off, 16));
            mn[i] = fmaxf(m_i[i], rm);
            alpha[i] = __expf(m_i[i] - mn[i]);
        }
#pragma unroll
        for (int i = 0; i < 4; i++) {
            rs[i] = 0.f;
#pragma unroll
            for (int j = 0; j < 4; j++) {
                p[i][j] = __expf(s[i][j] - mn[i]);
                rs[i] += p[i][j];
            }
#pragma unroll
            for (int off = 8; off > 0; off >>= 1)
                rs[i] += __shfl_xor_sync(0xffffffffu, rs[i], off, 16);
            l_i[i] = l_i[i] * alpha[i] + rs[i];
            m_i[i] = mn[i];
#pragma unroll
            for (int j = 0; j < 4; j++) oa[i][j] *= alpha[i];
        }

        // stage P (previous PV consumers finished at loop-bottom sync)
#pragma unroll
        for (int i = 0; i < 4; i++)
#pragma unroll
            for (int j = 0; j < 4; j++)
                Ps[(tr * 4 + i) * PAD + tc * 4 + j] = p[i][j];
        __syncthreads();

        // O += P @ V
#pragma unroll 8
        for (int c = 0; c < 64; c++) {
            float a[4], bb[4];
#pragma unroll
            for (int i = 0; i < 4; i++) a[i]  = Ps[(tr * 4 + i) * PAD + c];
#pragma unroll
            for (int j = 0; j < 4; j++) bb[j] = Vs[c * PAD + tc * 4 + j];
#pragma unroll
            for (int i = 0; i < 4; i++)
#pragma unroll
                for (int j = 0; j < 4; j++)
                    oa[i][j] = fmaf(a[i], bb[j], oa[i][j]);
        }
        __syncthreads();
    }

    float* ob = o + ((size_t)(b * SEQ + mt * 64)) * DIM + h * HD;
#pragma unroll
    for (int i = 0; i < 4; i++) {
        float inv = 1.f / l_i[i];
#pragma unroll
        for (int j = 0; j < 4; j++)
            ob[(size_t)(tr * 4 + i) * DIM + tc * 4 + j] = oa[i][j] * inv;
    }
}

// ---------------------------------------------------------------------------
extern "C" void kernel_launch(void* const* d_in, const int* in_sizes, int n_in,
                              void* d_out, int out_size)
{
    (void)in_sizes; (void)n_in; (void)out_size;
    const float* Q  = (const float*)d_in[0];
    const float* K  = (const float*)d_in[1];
    const float* V  = (const float*)d_in[2];
    // d_in[3] = mask (causal, known statically — unused)
    const float* Wq = (const float*)d_in[4];
    const float* bq = (const float*)d_in[5];
    const float* Wk = (const float*)d_in[6];
    const float* bk = (const float*)d_in[7];
    const float* Wv = (const float*)d_in[8];
    const float* bv = (const float*)d_in[9];
    const float* Wo = (const float*)d_in[10];
    const float* bo = (const float*)d_in[11];

    float *gq, *gk, *gv, *gao;
    cudaGetSymbolAddress((void**)&gq,  g_q);
    cudaGetSymbolAddress((void**)&gk,  g_k);
    cudaGetSymbolAddress((void**)&gv,  g_v);
    cudaGetSymbolAddress((void**)&gao, g_ao);

    cudaFuncSetAttribute(attn_kernel,
                         cudaFuncAttributeMaxDynamicSharedMemorySize, ATTN_SMEM);

    dim3 gblk(DIM / 128, MROWS / 128);   // (8, 32)
    sgemm_nt_bias<<<gblk, 256>>>(Q, Wq, bq, gq, MROWS, DIM, DIM);
    sgemm_nt_bias<<<gblk, 256>>>(K, Wk, bk, gk, MROWS, DIM, DIM);
    sgemm_nt_bias<<<gblk, 256>>>(V, Wv, bv, gv, MROWS, DIM, DIM);

    attn_kernel<<<dim3(SEQ / 64, NH, BATCH), 256, ATTN_SMEM>>>(gq, gk, gv, gao);

    sgemm_nt_bias<<<gblk, 256>>>(gao, Wo, bo, (float*)d_out, MROWS, DIM, DIM);
}

// round 3
// speedup vs baseline: 1.2469x; 1.2469x over previous
#include <cuda_runtime.h>
#include <cuda_bf16.h>
#include <cstdint>

// Problem constants
#define BATCH 2
#define SEQ   2048
#define DIM   1024
#define NH    16
#define HD    64
#define MROWS (BATCH * SEQ)   // 4096

// ---------------------------------------------------------------------------
// Scratch (__device__ globals; allocation-free rule)
// ---------------------------------------------------------------------------
__device__ float g_q[MROWS * DIM];
__device__ float g_k[MROWS * DIM];
__device__ float g_v[MROWS * DIM];
__device__ float g_ao[MROWS * DIM];
__device__ __nv_bfloat16 g_ah[MROWS * DIM];   // split A hi
__device__ __nv_bfloat16 g_al[MROWS * DIM];   // split A lo
__device__ __nv_bfloat16 g_wh[DIM * DIM];     // split W hi
__device__ __nv_bfloat16 g_wl[DIM * DIM];     // split W lo

// ---------------------------------------------------------------------------
// helpers
// ---------------------------------------------------------------------------
__device__ __forceinline__ uint32_t smem_u32(const void* p) {
    uint32_t a;
    asm("{ .reg .u64 t; cvta.to.shared.u64 t, %1; cvt.u32.u64 %0, t; }"
        : "=r"(a) : "l"(p));
    return a;
}

__device__ __forceinline__ void cpa16(uint32_t s, const void* g) {
    asm volatile("cp.async.cg.shared.global [%0], [%1], 16;" :: "r"(s), "l"(g));
}

__device__ __forceinline__ void ldsm_x4(uint32_t (&r)[4], uint32_t addr) {
    asm volatile("ldmatrix.sync.aligned.m8n8.x4.shared.b16 {%0,%1,%2,%3}, [%4];"
        : "=r"(r[0]), "=r"(r[1]), "=r"(r[2]), "=r"(r[3]) : "r"(addr));
}

__device__ __forceinline__ void mma_bf16(float (&c)[4],
                                         const uint32_t (&a)[4],
                                         uint32_t b0, uint32_t b1) {
    asm volatile(
        "mma.sync.aligned.m16n8k16.row.col.f32.bf16.bf16.f32 "
        "{%0,%1,%2,%3}, {%4,%5,%6,%7}, {%8,%9}, {%0,%1,%2,%3};"
        : "+f"(c[0]), "+f"(c[1]), "+f"(c[2]), "+f"(c[3])
        : "r"(a[0]), "r"(a[1]), "r"(a[2]), "r"(a[3]), "r"(b0), "r"(b1));
}

// ---------------------------------------------------------------------------
// fp32 -> bf16 hi/lo split
// ---------------------------------------------------------------------------
__global__ __launch_bounds__(256) void split_bf16(
    const float* __restrict__ x, __nv_bfloat16* __restrict__ h,
    __nv_bfloat16* __restrict__ l, int n4)
{
    int i = blockIdx.x * 256 + threadIdx.x;
    if (i >= n4) return;
    float4 v = reinterpret_cast<const float4*>(x)[i];
    __nv_bfloat16 h0 = __float2bfloat16(v.x), h1 = __float2bfloat16(v.y);
    __nv_bfloat16 h2 = __float2bfloat16(v.z), h3 = __float2bfloat16(v.w);
    __nv_bfloat162 hh0, hh1, ll0, ll1;
    hh0.x = h0; hh0.y = h1; hh1.x = h2; hh1.y = h3;
    ll0.x = __float2bfloat16(v.x - __bfloat162float(h0));
    ll0.y = __float2bfloat16(v.y - __bfloat162float(h1));
    ll1.x = __float2bfloat16(v.z - __bfloat162float(h2));
    ll1.y = __float2bfloat16(v.w - __bfloat162float(h3));
    reinterpret_cast<__nv_bfloat162*>(h)[i * 2]     = hh0;
    reinterpret_cast<__nv_bfloat162*>(h)[i * 2 + 1] = hh1;
    reinterpret_cast<__nv_bfloat162*>(l)[i * 2]     = ll0;
    reinterpret_cast<__nv_bfloat162*>(l)[i * 2 + 1] = ll1;
}

// ---------------------------------------------------------------------------
// HMMA split-bf16 GEMM: C[4096,1024] = A[4096,1024] @ B[1024,1024]^T + bias
// BM=128, BN=128, BK=32, 256 threads (8 warps, 4x2), warp tile 32x64.
// 2-stage cp.async pipeline. Smem rows padded to 80B (conflict-free ldmatrix).
// ---------------------------------------------------------------------------
#define BKC        32
#define ROWB       80                 // bytes per smem row (32 bf16 + 8 pad)
#define BUF_B      (128 * ROWB)       // 10240 B per operand buffer
#define STAGE_B    (4 * BUF_B)        // Ah, Al, Bh, Bl
#define GEMM_SMEM  (2 * STAGE_B)      // 81920 B

__global__ __launch_bounds__(256) void gemm_mma(
    const __nv_bfloat16* __restrict__ Ah, const __nv_bfloat16* __restrict__ Al,
    const __nv_bfloat16* __restrict__ Bh, const __nv_bfloat16* __restrict__ Bl,
    const float* __restrict__ bias, float* __restrict__ C)
{
    extern __shared__ char smem[];
    const uint32_t sb = smem_u32(smem);
    const int tid  = threadIdx.x;
    const int lane = tid & 31;
    const int warp = tid >> 5;
    const int wm = (warp >> 1) * 32;   // warp M offset (4 warps)
    const int wn = (warp & 1) * 64;    // warp N offset (2 warps)
    const int bm = blockIdx.y * 128;
    const int bn = blockIdx.x * 128;

    const __nv_bfloat16* gsrc[4] = {
        Ah + (size_t)bm * DIM, Al + (size_t)bm * DIM,
        Bh + (size_t)bn * DIM, Bl + (size_t)bn * DIM };

    float acc[2][8][4];
#pragma unroll
    for (int i = 0; i < 2; i++)
#pragma unroll
        for (int j = 0; j < 8; j++)
#pragma unroll
            for (int q = 0; q < 4; q++) acc[i][j][q] = 0.f;

    // gmem->smem stage loader: 128 rows x 64B per buffer, 4 buffers
    const int lrow = tid >> 2;          // 0..63 -> two rows per thread
    const int lseg = (tid & 3) * 16;    // byte seg within 64B chunk
    auto load_stage = [&](int ck, int st) {
        const uint32_t so = sb + st * STAGE_B;
        const size_t kb = (size_t)ck * BKC;
#pragma unroll
        for (int buf = 0; buf < 4; buf++) {
            const char* g = (const char*)(gsrc[buf] + kb);
            uint32_t s = so + buf * BUF_B;
#pragma unroll
            for (int half = 0; half < 2; half++) {
                int r = lrow + half * 64;
                cpa16(s + r * ROWB + lseg, g + (size_t)r * (DIM * 2) + lseg);
            }
        }
    };

    // ldmatrix address pre-compute
    // A (x4): lanes 0-15 -> rows, lanes 16-31 -> rows, +16B
    const int aRow = lane & 15;
    const int aOff = (lane >> 4) * 16;
    // B (x4): q = lane>>3: rows n0+(q>>1)*8+(lane&7), koff (q&1)*16
    const int bRow = ((lane >> 4) & 1) * 8 + (lane & 7);
    const int bOff = ((lane >> 3) & 1) * 16;

    load_stage(0, 0);
    asm volatile("cp.async.commit_group;" ::: "memory");

    for (int ck = 0; ck < DIM / BKC; ck++) {
        if (ck + 1 < DIM / BKC) {
            load_stage(ck + 1, (ck + 1) & 1);
            asm volatile("cp.async.commit_group;" ::: "memory");
            asm volatile("cp.async.wait_group 1;" ::: "memory");
        } else {
            asm volatile("cp.async.wait_group 0;" ::: "memory");
        }
        __syncthreads();

        const uint32_t so = sb + (ck & 1) * STAGE_B;
        const uint32_t sAh = so;
        const uint32_t sAl = so + BUF_B;
        const uint32_t sBh = so + 2 * BUF_B;
        const uint32_t sBl = so + 3 * BUF_B;

#pragma unroll
        for (int ks = 0; ks < 2; ks++) {
            const int koff = ks * 32;
            uint32_t ah[2][4], al[2][4];
#pragma unroll
            for (int mi = 0; mi < 2; mi++) {
                uint32_t ra = (wm + mi * 16 + aRow) * ROWB + koff + aOff;
                ldsm_x4(ah[mi], sAh + ra);
                ldsm_x4(al[mi], sAl + ra);
            }
#pragma unroll
            for (int np = 0; np < 4; np++) {
                uint32_t rb = (wn + np * 16 + bRow) * ROWB + koff + bOff;
                uint32_t bh[4], bl[4];
                ldsm_x4(bh, sBh + rb);
                ldsm_x4(bl, sBl + rb);
#pragma unroll
                for (int sub = 0; sub < 2; sub++) {
                    uint32_t bh0 = bh[2 * sub], bh1 = bh[2 * sub + 1];
                    uint32_t bl0 = bl[2 * sub], bl1 = bl[2 * sub + 1];
#pragma unroll
                    for (int mi = 0; mi < 2; mi++) {
                        mma_bf16(acc[mi][np * 2 + sub], ah[mi], bh0, bh1);
                        mma_bf16(acc[mi][np * 2 + sub], ah[mi], bl0, bl1);
                        mma_bf16(acc[mi][np * 2 + sub], al[mi], bh0, bh1);
                    }
                }
            }
        }
        __syncthreads();
    }

    // epilogue: c frag layout m16n8: (g, 2tg),(g,2tg+1),(g+8,2tg),(g+8,2tg+1)
    const int g  = lane >> 2;
    const int tg = lane & 3;
#pragma unroll
    for (int mi = 0; mi < 2; mi++) {
#pragma unroll
        for (int nt = 0; nt < 8; nt++) {
            int col = bn + wn + nt * 8 + tg * 2;
            float b0 = __ldg(&bias[col]), b1 = __ldg(&bias[col + 1]);
            int r0 = bm + wm + mi * 16 + g;
            float2 v0 = make_float2(acc[mi][nt][0] + b0, acc[mi][nt][1] + b1);
            float2 v1 = make_float2(acc[mi][nt][2] + b0, acc[mi][nt][3] + b1);
            *reinterpret_cast<float2*>(&C[(size_t)r0 * DIM + col])       = v0;
            *reinterpret_cast<float2*>(&C[(size_t)(r0 + 8) * DIM + col]) = v1;
        }
    }
}

// ---------------------------------------------------------------------------
// Causal flash attention, fp32, vectorized LDS (float4 k-blocking).
// BM = BN = 64, 256 threads, 4x4 per thread, online softmax.
// ---------------------------------------------------------------------------
#define PAD 68
#define ATTN_SMEM (4 * 64 * PAD * (int)sizeof(float))

__global__ __launch_bounds__(256) void attn_kernel(
    const float* __restrict__ q, const float* __restrict__ k,
    const float* __restrict__ v, float* __restrict__ o)
{
    extern __shared__ float sm[];
    float* Qs = sm;                  // [64][PAD]
    float* Ks = sm + 64 * PAD;
    float* Vs = sm + 2 * 64 * PAD;
    float* Ps = sm + 3 * 64 * PAD;

    const int mt = blockIdx.x;
    const int h  = blockIdx.y;
    const int b  = blockIdx.z;
    const int t  = threadIdx.x;
    const int tr = t >> 4;
    const int tc = t & 15;

    const float* qb = q + ((size_t)(b * SEQ + mt * 64)) * DIM + h * HD;
    for (int i = t; i < 64 * 16; i += 256) {
        int r = i >> 4, c4 = (i & 15) * 4;
        *reinterpret_cast<float4*>(&Qs[r * PAD + c4]) =
            *reinterpret_cast<const float4*>(&qb[(size_t)r * DIM + c4]);
    }

    float m_i[4], l_i[4], oa[4][4];
#pragma unroll
    for (int i = 0; i < 4; i++) {
        m_i[i] = -1e30f; l_i[i] = 0.f;
#pragma unroll
        for (int j = 0; j < 4; j++) oa[i][j] = 0.f;
    }
    __syncthreads();

    for (int nt = 0; nt <= mt; nt++) {
        const float* kb = k + ((size_t)(b * SEQ + nt * 64)) * DIM + h * HD;
        const float* vb = v + ((size_t)(b * SEQ + nt * 64)) * DIM + h * HD;
        for (int i = t; i < 64 * 16; i += 256) {
            int r = i >> 4, c4 = (i & 15) * 4;
            *reinterpret_cast<float4*>(&Ks[r * PAD + c4]) =
                *reinterpret_cast<const float4*>(&kb[(size_t)r * DIM + c4]);
            *reinterpret_cast<float4*>(&Vs[r * PAD + c4]) =
                *reinterpret_cast<const float4*>(&vb[(size_t)r * DIM + c4]);
        }
        __syncthreads();

        // S = Q @ K^T, float4 k-blocking
        float s[4][4] = {};
#pragma unroll 4
        for (int k4 = 0; k4 < 16; k4++) {
            float4 b4[4];
#pragma unroll
            for (int j = 0; j < 4; j++)
                b4[j] = *reinterpret_cast<const float4*>(&Ks[(tc * 4 + j) * PAD + k4 * 4]);
#pragma unroll
            for (int i = 0; i < 4; i++) {
                float4 a = *reinterpret_cast<const float4*>(&Qs[(tr * 4 + i) * PAD + k4 * 4]);
#pragma unroll
                for (int j = 0; j < 4; j++) {
                    s[i][j] = fmaf(a.x, b4[j].x, s[i][j]);
                    s[i][j] = fmaf(a.y, b4[j].y, s[i][j]);
                    s[i][j] = fmaf(a.z, b4[j].z, s[i][j]);
                    s[i][j] = fmaf(a.w, b4[j].w, s[i][j]);
                }
            }
        }

#pragma unroll
        for (int i = 0; i < 4; i++)
#pragma unroll
            for (int j = 0; j < 4; j++) {
                s[i][j] *= 0.125f;
                if (nt == mt && (tc * 4 + j) > (tr * 4 + i)) s[i][j] = -1e9f;
            }

        // online softmax
#pragma unroll
        for (int i = 0; i < 4; i++) {
            float rm = fmaxf(fmaxf(s[i][0], s[i][1]), fmaxf(s[i][2], s[i][3]));
#pragma unroll
            for (int off = 8; off > 0; off >>= 1)
                rm = fmaxf(rm, __shfl_xor_sync(0xffffffffu, rm, off, 16));
            float mn = fmaxf(m_i[i], rm);
            float alpha = __expf(m_i[i] - mn);
            float p0 = __expf(s[i][0] - mn), p1 = __expf(s[i][1] - mn);
            float p2 = __expf(s[i][2] - mn), p3 = __expf(s[i][3] - mn);
            float rs = p0 + p1 + p2 + p3;
#pragma unroll
            for (int off = 8; off > 0; off >>= 1)
                rs += __shfl_xor_sync(0xffffffffu, rs, off, 16);
            l_i[i] = l_i[i] * alpha + rs;
            m_i[i] = mn;
#pragma unroll
            for (int j = 0; j < 4; j++) oa[i][j] *= alpha;
            *reinterpret_cast<float4*>(&Ps[(tr * 4 + i) * PAD + tc * 4]) =
                make_float4(p0, p1, p2, p3);
        }
        __syncthreads();

        // O += P @ V, float4 k-blocking
#pragma unroll 4
        for (int c4 = 0; c4 < 16; c4++) {
            float4 vb4[4];
#pragma unroll
            for (int cc = 0; cc < 4; cc++)
                vb4[cc] = *reinterpret_cast<const float4*>(&Vs[(c4 * 4 + cc) * PAD + tc * 4]);
#pragma unroll
            for (int i = 0; i < 4; i++) {
                float4 a = *reinterpret_cast<const float4*>(&Ps[(tr * 4 + i) * PAD + c4 * 4]);
                oa[i][0] = fmaf(a.x, vb4[0].x, oa[i][0]);
                oa[i][1] = fmaf(a.x, vb4[0].y, oa[i][1]);
                oa[i][2] = fmaf(a.x, vb4[0].z, oa[i][2]);
                oa[i][3] = fmaf(a.x, vb4[0].w, oa[i][3]);
                oa[i][0] = fmaf(a.y, vb4[1].x, oa[i][0]);
                oa[i][1] = fmaf(a.y, vb4[1].y, oa[i][1]);
                oa[i][2] = fmaf(a.y, vb4[1].z, oa[i][2]);
                oa[i][3] = fmaf(a.y, vb4[1].w, oa[i][3]);
                oa[i][0] = fmaf(a.z, vb4[2].x, oa[i][0]);
                oa[i][1] = fmaf(a.z, vb4[2].y, oa[i][1]);
                oa[i][2] = fmaf(a.z, vb4[2].z, oa[i][2]);
                oa[i][3] = fmaf(a.z, vb4[2].w, oa[i][3]);
                oa[i][0] = fmaf(a.w, vb4[3].x, oa[i][0]);
                oa[i][1] = fmaf(a.w, vb4[3].y, oa[i][1]);
                oa[i][2] = fmaf(a.w, vb4[3].z, oa[i][2]);
                oa[i][3] = fmaf(a.w, vb4[3].w, oa[i][3]);
            }
        }
        __syncthreads();
    }

    float* ob = o + ((size_t)(b * SEQ + mt * 64)) * DIM + h * HD;
#pragma unroll
    for (int i = 0; i < 4; i++) {
        float inv = 1.f / l_i[i];
        float4 ov = make_float4(oa[i][0] * inv, oa[i][1] * inv, oa[i][2] * inv, oa[i][3] * inv);
        *reinterpret_cast<float4*>(&ob[(size_t)(tr * 4 + i) * DIM + tc * 4]) = ov;
    }
}

// ---------------------------------------------------------------------------
extern "C" void kernel_launch(void* const* d_in, const int* in_sizes, int n_in,
                              void* d_out, int out_size)
{
    (void)in_sizes; (void)n_in; (void)out_size;
    const float* Q  = (const float*)d_in[0];
    const float* K  = (const float*)d_in[1];
    const float* V  = (const float*)d_in[2];
    const float* Wq = (const float*)d_in[4];
    const float* bq = (const float*)d_in[5];
    const float* Wk = (const float*)d_in[6];
    const float* bk = (const float*)d_in[7];
    const float* Wv = (const float*)d_in[8];
    const float* bv = (const float*)d_in[9];
    const float* Wo = (const float*)d_in[10];
    const float* bo = (const float*)d_in[11];

    float *gq, *gk, *gv, *gao;
    __nv_bfloat16 *ah, *al, *wh, *wl;
    cudaGetSymbolAddress((void**)&gq,  g_q);
    cudaGetSymbolAddress((void**)&gk,  g_k);
    cudaGetSymbolAddress((void**)&gv,  g_v);
    cudaGetSymbolAddress((void**)&gao, g_ao);
    cudaGetSymbolAddress((void**)&ah,  g_ah);
    cudaGetSymbolAddress((void**)&al,  g_al);
    cudaGetSymbolAddress((void**)&wh,  g_wh);
    cudaGetSymbolAddress((void**)&wl,  g_wl);

    cudaFuncSetAttribute(attn_kernel,
                         cudaFuncAttributeMaxDynamicSharedMemorySize, ATTN_SMEM);
    cudaFuncSetAttribute(gemm_mma,
                         cudaFuncAttributeMaxDynamicSharedMemorySize, GEMM_SMEM);

    const int nA4 = MROWS * DIM / 4;
    const int nW4 = DIM * DIM / 4;
    dim3 ggrid(DIM / 128, MROWS / 128);   // (8, 32)

    // Q projection
    split_bf16<<<(nA4 + 255) / 256, 256>>>(Q,  ah, al, nA4);
    split_bf16<<<(nW4 + 255) / 256, 256>>>(Wq, wh, wl, nW4);
    gemm_mma<<<ggrid, 256, GEMM_SMEM>>>(ah, al, wh, wl, bq, gq);
    // K projection
    split_bf16<<<(nA4 + 255) / 256, 256>>>(K,  ah, al, nA4);
    split_bf16<<<(nW4 + 255) / 256, 256>>>(Wk, wh, wl, nW4);
    gemm_mma<<<ggrid, 256, GEMM_SMEM>>>(ah, al, wh, wl, bk, gk);
    // V projection
    split_bf16<<<(nA4 + 255) / 256, 256>>>(V,  ah, al, nA4);
    split_bf16<<<(nW4 + 255) / 256, 256>>>(Wv, wh, wl, nW4);
    gemm_mma<<<ggrid, 256, GEMM_SMEM>>>(ah, al, wh, wl, bv, gv);

    // attention
    attn_kernel<<<dim3(SEQ / 64, NH, BATCH), 256, ATTN_SMEM>>>(gq, gk, gv, gao);

    // output projection
    split_bf16<<<(nA4 + 255) / 256, 256>>>(gao, ah, al, nA4);
    split_bf16<<<(nW4 + 255) / 256, 256>>>(Wo,  wh, wl, nW4);
    gemm_mma<<<ggrid, 256, GEMM_SMEM>>>(ah, al, wh, wl, bo, (float*)d_out);
}

// round 4
// speedup vs baseline: 2.4549x; 1.9687x over previous
#include <cuda_runtime.h>
#include <cuda_bf16.h>
#include <cstdint>

// Problem constants
#define BATCH 2
#define SEQ   2048
#define DIM   1024
#define NH    16
#define HD    64
#define MROWS (BATCH * SEQ)   // 4096

// ---------------------------------------------------------------------------
// Scratch (__device__ globals; allocation-free rule)
// ---------------------------------------------------------------------------
__device__ float g_q[MROWS * DIM];
__device__ float g_k[MROWS * DIM];
__device__ float g_v[MROWS * DIM];
__device__ float g_ao[MROWS * DIM];
__device__ __nv_bfloat16 g_ah[MROWS * DIM];   // GEMM A hi
__device__ __nv_bfloat16 g_al[MROWS * DIM];   // GEMM A lo
__device__ __nv_bfloat16 g_wh[DIM * DIM];     // GEMM W hi
__device__ __nv_bfloat16 g_wl[DIM * DIM];     // GEMM W lo
__device__ __nv_bfloat16 g_qh[MROWS * DIM];   // attn q hi
__device__ __nv_bfloat16 g_ql[MROWS * DIM];   // attn q lo
__device__ __nv_bfloat16 g_kh[MROWS * DIM];   // attn k hi
__device__ __nv_bfloat16 g_kl[MROWS * DIM];   // attn k lo

// ---------------------------------------------------------------------------
// helpers
// ---------------------------------------------------------------------------
__device__ __forceinline__ uint32_t smem_u32(const void* p) {
    uint32_t a;
    asm("{ .reg .u64 t; cvta.to.shared.u64 t, %1; cvt.u32.u64 %0, t; }"
        : "=r"(a) : "l"(p));
    return a;
}

__device__ __forceinline__ void cpa16(uint32_t s, const void* g) {
    asm volatile("cp.async.cg.shared.global [%0], [%1], 16;" :: "r"(s), "l"(g));
}

__device__ __forceinline__ void ldsm_x4(uint32_t (&r)[4], uint32_t addr) {
    asm volatile("ldmatrix.sync.aligned.m8n8.x4.shared.b16 {%0,%1,%2,%3}, [%4];"
        : "=r"(r[0]), "=r"(r[1]), "=r"(r[2]), "=r"(r[3]) : "r"(addr));
}

__device__ __forceinline__ void mma_bf16(float (&c)[4],
                                         const uint32_t (&a)[4],
                                         uint32_t b0, uint32_t b1) {
    asm volatile(
        "mma.sync.aligned.m16n8k16.row.col.f32.bf16.bf16.f32 "
        "{%0,%1,%2,%3}, {%4,%5,%6,%7}, {%8,%9}, {%0,%1,%2,%3};"
        : "+f"(c[0]), "+f"(c[1]), "+f"(c[2]), "+f"(c[3])
        : "r"(a[0]), "r"(a[1]), "r"(a[2]), "r"(a[3]), "r"(b0), "r"(b1));
}

// split a pair of fp32 into packed bf16x2 hi and lo
__device__ __forceinline__ void split2(float a, float b, uint32_t& hi, uint32_t& lo) {
    __nv_bfloat162 h2 = __floats2bfloat162_rn(a, b);
    float ax = __bfloat162float(h2.x), bx = __bfloat162float(h2.y);
    __nv_bfloat162 l2 = __floats2bfloat162_rn(a - ax, b - bx);
    hi = *reinterpret_cast<uint32_t*>(&h2);
    lo = *reinterpret_cast<uint32_t*>(&l2);
}

// ---------------------------------------------------------------------------
// fp32 -> bf16 hi/lo split
// ---------------------------------------------------------------------------
__global__ __launch_bounds__(256) void split_bf16(
    const float* __restrict__ x, __nv_bfloat16* __restrict__ h,
    __nv_bfloat16* __restrict__ l, int n4)
{
    int i = blockIdx.x * 256 + threadIdx.x;
    if (i >= n4) return;
    float4 v = reinterpret_cast<const float4*>(x)[i];
    uint32_t h0, l0, h1, l1;
    split2(v.x, v.y, h0, l0);
    split2(v.z, v.w, h1, l1);
    reinterpret_cast<uint32_t*>(h)[i * 2]     = h0;
    reinterpret_cast<uint32_t*>(h)[i * 2 + 1] = h1;
    reinterpret_cast<uint32_t*>(l)[i * 2]     = l0;
    reinterpret_cast<uint32_t*>(l)[i * 2 + 1] = l1;
}

// ---------------------------------------------------------------------------
// HMMA split-bf16 GEMM: C[4096,1024] = A[4096,1024] @ B[1024,1024]^T + bias
// BM=128, BN=128, BK=32, 256 threads (8 warps, 4x2), warp tile 32x64.
// ---------------------------------------------------------------------------
#define BKC        32
#define ROWB       80
#define BUF_B      (128 * ROWB)
#define STAGE_B    (4 * BUF_B)
#define GEMM_SMEM  (2 * STAGE_B)

__global__ __launch_bounds__(256) void gemm_mma(
    const __nv_bfloat16* __restrict__ Ah, const __nv_bfloat16* __restrict__ Al,
    const __nv_bfloat16* __restrict__ Bh, const __nv_bfloat16* __restrict__ Bl,
    const float* __restrict__ bias, float* __restrict__ C)
{
    extern __shared__ char smem[];
    const uint32_t sb = smem_u32(smem);
    const int tid  = threadIdx.x;
    const int lane = tid & 31;
    const int warp = tid >> 5;
    const int wm = (warp >> 1) * 32;
    const int wn = (warp & 1) * 64;
    const int bm = blockIdx.y * 128;
    const int bn = blockIdx.x * 128;

    const __nv_bfloat16* gsrc[4] = {
        Ah + (size_t)bm * DIM, Al + (size_t)bm * DIM,
        Bh + (size_t)bn * DIM, Bl + (size_t)bn * DIM };

    float acc[2][8][4];
#pragma unroll
    for (int i = 0; i < 2; i++)
#pragma unroll
        for (int j = 0; j < 8; j++)
#pragma unroll
            for (int q = 0; q < 4; q++) acc[i][j][q] = 0.f;

    const int lrow = tid >> 2;
    const int lseg = (tid & 3) * 16;
    auto load_stage = [&](int ck, int st) {
        const uint32_t so = sb + st * STAGE_B;
        const size_t kb = (size_t)ck * BKC;
#pragma unroll
        for (int buf = 0; buf < 4; buf++) {
            const char* g = (const char*)(gsrc[buf] + kb);
            uint32_t s = so + buf * BUF_B;
#pragma unroll
            for (int half = 0; half < 2; half++) {
                int r = lrow + half * 64;
                cpa16(s + r * ROWB + lseg, g + (size_t)r * (DIM * 2) + lseg);
            }
        }
    };

    const int aRow = lane & 15;
    const int aOff = (lane >> 4) * 16;
    const int bRow = ((lane >> 4) & 1) * 8 + (lane & 7);
    const int bOff = ((lane >> 3) & 1) * 16;

    load_stage(0, 0);
    asm volatile("cp.async.commit_group;" ::: "memory");

    for (int ck = 0; ck < DIM / BKC; ck++) {
        if (ck + 1 < DIM / BKC) {
            load_stage(ck + 1, (ck + 1) & 1);
            asm volatile("cp.async.commit_group;" ::: "memory");
            asm volatile("cp.async.wait_group 1;" ::: "memory");
        } else {
            asm volatile("cp.async.wait_group 0;" ::: "memory");
        }
        __syncthreads();

        const uint32_t so = sb + (ck & 1) * STAGE_B;
        const uint32_t sAh = so;
        const uint32_t sAl = so + BUF_B;
        const uint32_t sBh = so + 2 * BUF_B;
        const uint32_t sBl = so + 3 * BUF_B;

#pragma unroll
        for (int ks = 0; ks < 2; ks++) {
            const int koff = ks * 32;
            uint32_t ah[2][4], al[2][4];
#pragma unroll
            for (int mi = 0; mi < 2; mi++) {
                uint32_t ra = (wm + mi * 16 + aRow) * ROWB + koff + aOff;
                ldsm_x4(ah[mi], sAh + ra);
                ldsm_x4(al[mi], sAl + ra);
            }
#pragma unroll
            for (int np = 0; np < 4; np++) {
                uint32_t rb = (wn + np * 16 + bRow) * ROWB + koff + bOff;
                uint32_t bh[4], bl[4];
                ldsm_x4(bh, sBh + rb);
                ldsm_x4(bl, sBl + rb);
#pragma unroll
                for (int sub = 0; sub < 2; sub++) {
                    uint32_t bh0 = bh[2 * sub], bh1 = bh[2 * sub + 1];
                    uint32_t bl0 = bl[2 * sub], bl1 = bl[2 * sub + 1];
#pragma unroll
                    for (int mi = 0; mi < 2; mi++) {
                        mma_bf16(acc[mi][np * 2 + sub], ah[mi], bh0, bh1);
                        mma_bf16(acc[mi][np * 2 + sub], ah[mi], bl0, bl1);
                        mma_bf16(acc[mi][np * 2 + sub], al[mi], bh0, bh1);
                    }
                }
            }
        }
        __syncthreads();
    }

    const int g  = lane >> 2;
    const int tg = lane & 3;
#pragma unroll
    for (int mi = 0; mi < 2; mi++) {
#pragma unroll
        for (int nt = 0; nt < 8; nt++) {
            int col = bn + wn + nt * 8 + tg * 2;
            float b0 = __ldg(&bias[col]), b1 = __ldg(&bias[col + 1]);
            int r0 = bm + wm + mi * 16 + g;
            float2 v0 = make_float2(acc[mi][nt][0] + b0, acc[mi][nt][1] + b1);
            float2 v1 = make_float2(acc[mi][nt][2] + b0, acc[mi][nt][3] + b1);
            *reinterpret_cast<float2*>(&C[(size_t)r0 * DIM + col])       = v0;
            *reinterpret_cast<float2*>(&C[(size_t)(r0 + 8) * DIM + col]) = v1;
        }
    }
}

// ---------------------------------------------------------------------------
// HMMA flash attention, split-bf16, causal.
// CTA: 128 q-rows x 8 warps (16 rows each), KV tile = 64 keys.
// Smem rows padded to 144B (conflict-free ldmatrix).
// ---------------------------------------------------------------------------
#define AB_ROWB 144
#define S_QH 0
#define S_QL 18432
#define S_KH 36864
#define S_KL 46080
#define S_VH 55296
#define S_VL 64512
#define ATTN_SMEM 73728

__global__ __launch_bounds__(256, 1) void attn_mma(
    const __nv_bfloat16* __restrict__ qh, const __nv_bfloat16* __restrict__ ql,
    const __nv_bfloat16* __restrict__ kh, const __nv_bfloat16* __restrict__ kl,
    const float* __restrict__ v, float* __restrict__ o)
{
    extern __shared__ char smem[];
    const uint32_t sb = smem_u32(smem);
    const int tid = threadIdx.x, lane = tid & 31, warp = tid >> 5;
    const int g = lane >> 2, tg = lane & 3;
    const int blk = blockIdx.x, h = blockIdx.y, b = blockIdx.z;
    const int qbase = blk * 128;
    const int wq = warp * 16;
    const int hc = h * HD;

    const int aRow = lane & 15, aOff = (lane >> 4) * 16;
    const int bRow = ((lane >> 4) & 1) * 8 + (lane & 7);
    const int bOff = ((lane >> 3) & 1) * 16;

    // ---- load Q tile (128 x 64) hi/lo ----
    for (int i = tid; i < 1024; i += 256) {
        int r = i >> 3; int seg = (i & 7) * 16;
        uint32_t d = (uint32_t)r * AB_ROWB + seg;
        size_t gofs = ((size_t)(b * SEQ + qbase + r) * DIM + hc) * 2 + seg;
        cpa16(sb + S_QH + d, (const char*)qh + gofs);
        cpa16(sb + S_QL + d, (const char*)ql + gofs);
    }
    asm volatile("cp.async.commit_group;" ::: "memory");
    asm volatile("cp.async.wait_group 0;" ::: "memory");
    __syncthreads();

    const uint32_t raBase = (uint32_t)(wq + aRow) * AB_ROWB + aOff;
    uint32_t qfh[4][4];
#pragma unroll
    for (int ks = 0; ks < 4; ks++)
        ldsm_x4(qfh[ks], sb + S_QH + raBase + ks * 32);

    float m0 = -1e30f, m1 = -1e30f, l0 = 0.f, l1 = 0.f;
    float oacc[8][4];
#pragma unroll
    for (int nt = 0; nt < 8; nt++)
#pragma unroll
        for (int q2 = 0; q2 < 4; q2++) oacc[nt][q2] = 0.f;

    const int jmax = 2 * blk + 1;
    for (int j = 0; j <= jmax; j++) {
        // K tile (64 x 64) hi/lo via cp.async
        for (int i = tid; i < 512; i += 256) {
            int r = i >> 3; int seg = (i & 7) * 16;
            uint32_t d = (uint32_t)r * AB_ROWB + seg;
            size_t gofs = ((size_t)(b * SEQ + j * 64 + r) * DIM + hc) * 2 + seg;
            cpa16(sb + S_KH + d, (const char*)kh + gofs);
            cpa16(sb + S_KL + d, (const char*)kl + gofs);
        }
        asm volatile("cp.async.commit_group;" ::: "memory");
        // V tile: fp32 load, split, store TRANSPOSED [dim][key]
        for (int i = tid; i < 2048; i += 256) {
            int key = i & 63, dp = (i >> 6) * 2;
            float2 vv = *reinterpret_cast<const float2*>(
                v + (size_t)(b * SEQ + j * 64 + key) * DIM + hc + dp);
            uint32_t hi2, lo2; split2(vv.x, vv.y, hi2, lo2);
            __nv_bfloat162 hh = *reinterpret_cast<__nv_bfloat162*>(&hi2);
            __nv_bfloat162 ll = *reinterpret_cast<__nv_bfloat162*>(&lo2);
            *(__nv_bfloat16*)(smem + S_VH + dp * AB_ROWB + key * 2)       = hh.x;
            *(__nv_bfloat16*)(smem + S_VH + (dp + 1) * AB_ROWB + key * 2) = hh.y;
            *(__nv_bfloat16*)(smem + S_VL + dp * AB_ROWB + key * 2)       = ll.x;
            *(__nv_bfloat16*)(smem + S_VL + (dp + 1) * AB_ROWB + key * 2) = ll.y;
        }
        asm volatile("cp.async.wait_group 0;" ::: "memory");
        __syncthreads();

        if (qbase + wq + 15 >= j * 64) {     // warp-uniform
            // ---- S = Q @ K^T (keys = n, dim = k) ----
            float sc[8][4];
#pragma unroll
            for (int nt = 0; nt < 8; nt++)
#pragma unroll
                for (int q2 = 0; q2 < 4; q2++) sc[nt][q2] = 0.f;
#pragma unroll
            for (int ks = 0; ks < 4; ks++) {
                uint32_t qlf[4];
                ldsm_x4(qlf, sb + S_QL + raBase + ks * 32);
#pragma unroll
                for (int np = 0; np < 4; np++) {
                    uint32_t rb = (uint32_t)(np * 16 + bRow) * AB_ROWB + ks * 32 + bOff;
                    uint32_t bh4[4], bl4[4];
                    ldsm_x4(bh4, sb + S_KH + rb);
                    ldsm_x4(bl4, sb + S_KL + rb);
#pragma unroll
                    for (int sub = 0; sub < 2; sub++) {
                        mma_bf16(sc[np * 2 + sub], qfh[ks], bh4[2 * sub], bh4[2 * sub + 1]);
                        mma_bf16(sc[np * 2 + sub], qfh[ks], bl4[2 * sub], bl4[2 * sub + 1]);
                        mma_bf16(sc[np * 2 + sub], qlf,     bh4[2 * sub], bh4[2 * sub + 1]);
                    }
                }
            }

            // ---- scale + causal mask ----
            const int row0 = qbase + wq + g, row1 = row0 + 8;
#pragma unroll
            for (int nt = 0; nt < 8; nt++) {
                int kc = j * 64 + nt * 8 + 2 * tg;
                sc[nt][0] = (kc     <= row0) ? sc[nt][0] * 0.125f : -1e30f;
                sc[nt][1] = (kc + 1 <= row0) ? sc[nt][1] * 0.125f : -1e30f;
                sc[nt][2] = (kc     <= row1) ? sc[nt][2] * 0.125f : -1e30f;
                sc[nt][3] = (kc + 1 <= row1) ? sc[nt][3] * 0.125f : -1e30f;
            }

            // ---- online softmax ----
            float rm0 = -1e30f, rm1 = -1e30f;
#pragma unroll
            for (int nt = 0; nt < 8; nt++) {
                rm0 = fmaxf(rm0, fmaxf(sc[nt][0], sc[nt][1]));
                rm1 = fmaxf(rm1, fmaxf(sc[nt][2], sc[nt][3]));
            }
            rm0 = fmaxf(rm0, __shfl_xor_sync(0xffffffffu, rm0, 1));
            rm0 = fmaxf(rm0, __shfl_xor_sync(0xffffffffu, rm0, 2));
            rm1 = fmaxf(rm1, __shfl_xor_sync(0xffffffffu, rm1, 1));
            rm1 = fmaxf(rm1, __shfl_xor_sync(0xffffffffu, rm1, 2));
            float mn0 = fmaxf(m0, rm0), mn1 = fmaxf(m1, rm1);
            float al0 = __expf(m0 - mn0), al1 = __expf(m1 - mn1);
            m0 = mn0; m1 = mn1;
            float rs0 = 0.f, rs1 = 0.f;
#pragma unroll
            for (int nt = 0; nt < 8; nt++) {
                sc[nt][0] = __expf(sc[nt][0] - mn0);
                sc[nt][1] = __expf(sc[nt][1] - mn0);
                sc[nt][2] = __expf(sc[nt][2] - mn1);
                sc[nt][3] = __expf(sc[nt][3] - mn1);
                rs0 += sc[nt][0] + sc[nt][1];
                rs1 += sc[nt][2] + sc[nt][3];
            }
            rs0 += __shfl_xor_sync(0xffffffffu, rs0, 1);
            rs0 += __shfl_xor_sync(0xffffffffu, rs0, 2);
            rs1 += __shfl_xor_sync(0xffffffffu, rs1, 1);
            rs1 += __shfl_xor_sync(0xffffffffu, rs1, 2);
            l0 = l0 * al0 + rs0;
            l1 = l1 * al1 + rs1;
#pragma unroll
            for (int nt = 0; nt < 8; nt++) {
                oacc[nt][0] *= al0; oacc[nt][1] *= al0;
                oacc[nt][2] *= al1; oacc[nt][3] *= al1;
            }

            // ---- O += P @ V  (dims = n, keys = k) ----
#pragma unroll
            for (int ks = 0; ks < 4; ks++) {
                uint32_t pah[4], pal[4];
                split2(sc[2 * ks][0],     sc[2 * ks][1],     pah[0], pal[0]);
                split2(sc[2 * ks][2],     sc[2 * ks][3],     pah[1], pal[1]);
                split2(sc[2 * ks + 1][0], sc[2 * ks + 1][1], pah[2], pal[2]);
                split2(sc[2 * ks + 1][2], sc[2 * ks + 1][3], pah[3], pal[3]);
#pragma unroll
                for (int nd = 0; nd < 4; nd++) {
                    uint32_t rb = (uint32_t)(nd * 16 + bRow) * AB_ROWB + ks * 32 + bOff;
                    uint32_t vh4[4], vl4[4];
                    ldsm_x4(vh4, sb + S_VH + rb);
                    ldsm_x4(vl4, sb + S_VL + rb);
#pragma unroll
                    for (int sub = 0; sub < 2; sub++) {
                        mma_bf16(oacc[nd * 2 + sub], pah, vh4[2 * sub], vh4[2 * sub + 1]);
                        mma_bf16(oacc[nd * 2 + sub], pah, vl4[2 * sub], vl4[2 * sub + 1]);
                        mma_bf16(oacc[nd * 2 + sub], pal, vh4[2 * sub], vh4[2 * sub + 1]);
                    }
                }
            }
        }
        __syncthreads();
    }

    // ---- epilogue ----
    const float inv0 = 1.f / l0, inv1 = 1.f / l1;
    const size_t row0g = (size_t)(b * SEQ + qbase + wq + g);
#pragma unroll
    for (int nt = 0; nt < 8; nt++) {
        int col = hc + nt * 8 + 2 * tg;
        *reinterpret_cast<float2*>(o + row0g * DIM + col) =
            make_float2(oacc[nt][0] * inv0, oacc[nt][1] * inv0);
        *reinterpret_cast<float2*>(o + (row0g + 8) * DIM + col) =
            make_float2(oacc[nt][2] * inv1, oacc[nt][3] * inv1);
    }
}

// ---------------------------------------------------------------------------
extern "C" void kernel_launch(void* const* d_in, const int* in_sizes, int n_in,
                              void* d_out, int out_size)
{
    (void)in_sizes; (void)n_in; (void)out_size;
    const float* Q  = (const float*)d_in[0];
    const float* K  = (const float*)d_in[1];
    const float* V  = (const float*)d_in[2];
    const float* Wq = (const float*)d_in[4];
    const float* bq = (const float*)d_in[5];
    const float* Wk = (const float*)d_in[6];
    const float* bk = (const float*)d_in[7];
    const float* Wv = (const float*)d_in[8];
    const float* bv = (const float*)d_in[9];
    const float* Wo = (const float*)d_in[10];
    const float* bo = (const float*)d_in[11];

    float *gq, *gk, *gv, *gao;
    __nv_bfloat16 *ah, *al, *wh, *wl, *qh, *ql, *kh, *kl;
    cudaGetSymbolAddress((void**)&gq,  g_q);
    cudaGetSymbolAddress((void**)&gk,  g_k);
    cudaGetSymbolAddress((void**)&gv,  g_v);
    cudaGetSymbolAddress((void**)&gao, g_ao);
    cudaGetSymbolAddress((void**)&ah,  g_ah);
    cudaGetSymbolAddress((void**)&al,  g_al);
    cudaGetSymbolAddress((void**)&wh,  g_wh);
    cudaGetSymbolAddress((void**)&wl,  g_wl);
    cudaGetSymbolAddress((void**)&qh,  g_qh);
    cudaGetSymbolAddress((void**)&ql,  g_ql);
    cudaGetSymbolAddress((void**)&kh,  g_kh);
    cudaGetSymbolAddress((void**)&kl,  g_kl);

    cudaFuncSetAttribute(gemm_mma,
                         cudaFuncAttributeMaxDynamicSharedMemorySize, GEMM_SMEM);
    cudaFuncSetAttribute(attn_mma,
                         cudaFuncAttributeMaxDynamicSharedMemorySize, ATTN_SMEM);

    const int nA4 = MROWS * DIM / 4;
    const int nW4 = DIM * DIM / 4;
    dim3 ggrid(DIM / 128, MROWS / 128);   // (8, 32)

    // projections
    split_bf16<<<(nA4 + 255) / 256, 256>>>(Q,  ah, al, nA4);
    split_bf16<<<(nW4 + 255) / 256, 256>>>(Wq, wh, wl, nW4);
    gemm_mma<<<ggrid, 256, GEMM_SMEM>>>(ah, al, wh, wl, bq, gq);

    split_bf16<<<(nA4 + 255) / 256, 256>>>(K,  ah, al, nA4);
    split_bf16<<<(nW4 + 255) / 256, 256>>>(Wk, wh, wl, nW4);
    gemm_mma<<<ggrid, 256, GEMM_SMEM>>>(ah, al, wh, wl, bk, gk);

    split_bf16<<<(nA4 + 255) / 256, 256>>>(V,  ah, al, nA4);
    split_bf16<<<(nW4 + 255) / 256, 256>>>(Wv, wh, wl, nW4);
    gemm_mma<<<ggrid, 256, GEMM_SMEM>>>(ah, al, wh, wl, bv, gv);

    // split projected q/k for attention
    split_bf16<<<(nA4 + 255) / 256, 256>>>(gq, qh, ql, nA4);
    split_bf16<<<(nA4 + 255) / 256, 256>>>(gk, kh, kl, nA4);

    // attention (HMMA)
    attn_mma<<<dim3(SEQ / 128, NH, BATCH), 256, ATTN_SMEM>>>(qh, ql, kh, kl, gv, gao);

    // output projection
    split_bf16<<<(nA4 + 255) / 256, 256>>>(gao, ah, al, nA4);
    split_bf16<<<(nW4 + 255) / 256, 256>>>(Wo,  wh, wl, nW4);
    gemm_mma<<<ggrid, 256, GEMM_SMEM>>>(ah, al, wh, wl, bo, (float*)d_out);
}

// round 5
// speedup vs baseline: 3.0157x; 1.2285x over previous
#include <cuda_runtime.h>
#include <cuda_bf16.h>
#include <cstdint>

// Problem constants
#define BATCH 2
#define SEQ   2048
#define DIM   1024
#define NH    16
#define HD    64
#define MROWS (BATCH * SEQ)   // 4096
#define ASZ   (MROWS * DIM)   // 4M elements
#define WSZ   (DIM * DIM)     // 1M elements

// ---------------------------------------------------------------------------
// Scratch (__device__ globals; allocation-free rule)
// ---------------------------------------------------------------------------
__device__ __nv_bfloat16 g_inh[3 * ASZ], g_inl[3 * ASZ];   // split inputs Q,K,V
__device__ __nv_bfloat16 g_pwh[4 * WSZ], g_pwl[4 * WSZ];   // split weights
__device__ __nv_bfloat16 g_oh[3 * ASZ],  g_ol[3 * ASZ];    // projected q,k,v hi/lo
__device__ __nv_bfloat16 g_aoh[ASZ],     g_aol[ASZ];       // attention out hi/lo

// ---------------------------------------------------------------------------
// helpers
// ---------------------------------------------------------------------------
__device__ __forceinline__ uint32_t smem_u32(const void* p) {
    uint32_t a;
    asm("{ .reg .u64 t; cvta.to.shared.u64 t, %1; cvt.u32.u64 %0, t; }"
        : "=r"(a) : "l"(p));
    return a;
}

__device__ __forceinline__ void cpa16(uint32_t s, const void* g) {
    asm volatile("cp.async.cg.shared.global [%0], [%1], 16;" :: "r"(s), "l"(g));
}

__device__ __forceinline__ void ldsm_x4(uint32_t (&r)[4], uint32_t addr) {
    asm volatile("ldmatrix.sync.aligned.m8n8.x4.shared.b16 {%0,%1,%2,%3}, [%4];"
        : "=r"(r[0]), "=r"(r[1]), "=r"(r[2]), "=r"(r[3]) : "r"(addr));
}

__device__ __forceinline__ void ldsm_x4_t(uint32_t (&r)[4], uint32_t addr) {
    asm volatile("ldmatrix.sync.aligned.m8n8.x4.trans.shared.b16 {%0,%1,%2,%3}, [%4];"
        : "=r"(r[0]), "=r"(r[1]), "=r"(r[2]), "=r"(r[3]) : "r"(addr));
}

__device__ __forceinline__ void mma_bf16(float (&c)[4],
                                         const uint32_t (&a)[4],
                                         uint32_t b0, uint32_t b1) {
    asm volatile(
        "mma.sync.aligned.m16n8k16.row.col.f32.bf16.bf16.f32 "
        "{%0,%1,%2,%3}, {%4,%5,%6,%7}, {%8,%9}, {%0,%1,%2,%3};"
        : "+f"(c[0]), "+f"(c[1]), "+f"(c[2]), "+f"(c[3])
        : "r"(a[0]), "r"(a[1]), "r"(a[2]), "r"(a[3]), "r"(b0), "r"(b1));
}

__device__ __forceinline__ void split2(float a, float b, uint32_t& hi, uint32_t& lo) {
    __nv_bfloat162 h2 = __floats2bfloat162_rn(a, b);
    float ax = __bfloat162float(h2.x), bx = __bfloat162float(h2.y);
    __nv_bfloat162 l2 = __floats2bfloat162_rn(a - ax, b - bx);
    hi = *reinterpret_cast<uint32_t*>(&h2);
    lo = *reinterpret_cast<uint32_t*>(&l2);
}

// ---------------------------------------------------------------------------
// fp32 -> bf16 hi/lo splits (batched over planes)
// ---------------------------------------------------------------------------
__global__ __launch_bounds__(256) void split_in3(
    const float* __restrict__ a, const float* __restrict__ b,
    const float* __restrict__ c, __nv_bfloat16* __restrict__ h,
    __nv_bfloat16* __restrict__ l)
{
    const int plane = blockIdx.y;
    const float* src = plane == 0 ? a : (plane == 1 ? b : c);
    int i = blockIdx.x * 256 + threadIdx.x;          // float4 index
    float4 v = reinterpret_cast<const float4*>(src)[i];
    uint32_t h0, l0, h1, l1;
    split2(v.x, v.y, h0, l0);
    split2(v.z, v.w, h1, l1);
    uint32_t* ph = reinterpret_cast<uint32_t*>(h + (size_t)plane * ASZ);
    uint32_t* pl = reinterpret_cast<uint32_t*>(l + (size_t)plane * ASZ);
    ph[i * 2] = h0; ph[i * 2 + 1] = h1;
    pl[i * 2] = l0; pl[i * 2 + 1] = l1;
}

__global__ __launch_bounds__(256) void split_w4(
    const float* __restrict__ a, const float* __restrict__ b,
    const float* __restrict__ c, const float* __restrict__ d,
    __nv_bfloat16* __restrict__ h, __nv_bfloat16* __restrict__ l)
{
    const int plane = blockIdx.y;
    const float* src = plane == 0 ? a : (plane == 1 ? b : (plane == 2 ? c : d));
    int i = blockIdx.x * 256 + threadIdx.x;
    float4 v = reinterpret_cast<const float4*>(src)[i];
    uint32_t h0, l0, h1, l1;
    split2(v.x, v.y, h0, l0);
    split2(v.z, v.w, h1, l1);
    uint32_t* ph = reinterpret_cast<uint32_t*>(h + (size_t)plane * WSZ);
    uint32_t* pl = reinterpret_cast<uint32_t*>(l + (size_t)plane * WSZ);
    ph[i * 2] = h0; ph[i * 2 + 1] = h1;
    pl[i * 2] = l0; pl[i * 2 + 1] = l1;
}

// ---------------------------------------------------------------------------
// HMMA split-bf16 GEMM: C[4096,1024] = A @ W^T + bias,  grid.z selects plane.
// Epilogue: fp32 (outF) or fused bf16 hi/lo split (outH/outL).
// ---------------------------------------------------------------------------
#define BKC        32
#define ROWB       80
#define BUF_B      (128 * ROWB)
#define STAGE_B    (4 * BUF_B)
#define GEMM_SMEM  (2 * STAGE_B)

__global__ __launch_bounds__(256) void gemm_mma(
    const __nv_bfloat16* __restrict__ Ah, const __nv_bfloat16* __restrict__ Al,
    const __nv_bfloat16* __restrict__ Wh, const __nv_bfloat16* __restrict__ Wl,
    const float* __restrict__ bias0, const float* __restrict__ bias1,
    const float* __restrict__ bias2,
    __nv_bfloat16* __restrict__ outH, __nv_bfloat16* __restrict__ outL,
    float* __restrict__ outF)
{
    extern __shared__ char smem[];
    const uint32_t sb = smem_u32(smem);
    const int tid  = threadIdx.x;
    const int lane = tid & 31;
    const int warp = tid >> 5;
    const int wm = (warp >> 1) * 32;
    const int wn = (warp & 1) * 64;
    const int bm = blockIdx.y * 128;
    const int bn = blockIdx.x * 128;
    const int z  = blockIdx.z;
    const float* bias = z == 0 ? bias0 : (z == 1 ? bias1 : bias2);

    const __nv_bfloat16* gsrc[4] = {
        Ah + (size_t)z * ASZ + (size_t)bm * DIM,
        Al + (size_t)z * ASZ + (size_t)bm * DIM,
        Wh + (size_t)z * WSZ + (size_t)bn * DIM,
        Wl + (size_t)z * WSZ + (size_t)bn * DIM };

    float acc[2][8][4];
#pragma unroll
    for (int i = 0; i < 2; i++)
#pragma unroll
        for (int j = 0; j < 8; j++)
#pragma unroll
            for (int q = 0; q < 4; q++) acc[i][j][q] = 0.f;

    const int lrow = tid >> 2;
    const int lseg = (tid & 3) * 16;
    auto load_stage = [&](int ck, int st) {
        const uint32_t so = sb + st * STAGE_B;
        const size_t kb = (size_t)ck * BKC;
#pragma unroll
        for (int buf = 0; buf < 4; buf++) {
            const char* g = (const char*)(gsrc[buf] + kb);
            uint32_t s = so + buf * BUF_B;
#pragma unroll
            for (int half = 0; half < 2; half++) {
                int r = lrow + half * 64;
                cpa16(s + r * ROWB + lseg, g + (size_t)r * (DIM * 2) + lseg);
            }
        }
    };

    const int aRow = lane & 15;
    const int aOff = (lane >> 4) * 16;
    const int bRow = ((lane >> 4) & 1) * 8 + (lane & 7);
    const int bOff = ((lane >> 3) & 1) * 16;

    load_stage(0, 0);
    asm volatile("cp.async.commit_group;" ::: "memory");

    for (int ck = 0; ck < DIM / BKC; ck++) {
        if (ck + 1 < DIM / BKC) {
            load_stage(ck + 1, (ck + 1) & 1);
            asm volatile("cp.async.commit_group;" ::: "memory");
            asm volatile("cp.async.wait_group 1;" ::: "memory");
        } else {
            asm volatile("cp.async.wait_group 0;" ::: "memory");
        }
        __syncthreads();

        const uint32_t so = sb + (ck & 1) * STAGE_B;
        const uint32_t sAh = so;
        const uint32_t sAl = so + BUF_B;
        const uint32_t sBh = so + 2 * BUF_B;
        const uint32_t sBl = so + 3 * BUF_B;

#pragma unroll
        for (int ks = 0; ks < 2; ks++) {
            const int koff = ks * 32;
            uint32_t ah[2][4], al[2][4];
#pragma unroll
            for (int mi = 0; mi < 2; mi++) {
                uint32_t ra = (wm + mi * 16 + aRow) * ROWB + koff + aOff;
                ldsm_x4(ah[mi], sAh + ra);
                ldsm_x4(al[mi], sAl + ra);
            }
#pragma unroll
            for (int np = 0; np < 4; np++) {
                uint32_t rb = (wn + np * 16 + bRow) * ROWB + koff + bOff;
                uint32_t bh[4], bl[4];
                ldsm_x4(bh, sBh + rb);
                ldsm_x4(bl, sBl + rb);
#pragma unroll
                for (int sub = 0; sub < 2; sub++) {
                    uint32_t bh0 = bh[2 * sub], bh1 = bh[2 * sub + 1];
                    uint32_t bl0 = bl[2 * sub], bl1 = bl[2 * sub + 1];
#pragma unroll
                    for (int mi = 0; mi < 2; mi++) {
                        mma_bf16(acc[mi][np * 2 + sub], ah[mi], bh0, bh1);
                        mma_bf16(acc[mi][np * 2 + sub], ah[mi], bl0, bl1);
                        mma_bf16(acc[mi][np * 2 + sub], al[mi], bh0, bh1);
                    }
                }
            }
        }
        __syncthreads();
    }

    const int g  = lane >> 2;
    const int tg = lane & 3;
    if (outF) {
#pragma unroll
        for (int mi = 0; mi < 2; mi++)
#pragma unroll
            for (int nt = 0; nt < 8; nt++) {
                int col = bn + wn + nt * 8 + tg * 2;
                float b0 = __ldg(&bias[col]), b1 = __ldg(&bias[col + 1]);
                int r0 = bm + wm + mi * 16 + g;
                *reinterpret_cast<float2*>(&outF[(size_t)r0 * DIM + col]) =
                    make_float2(acc[mi][nt][0] + b0, acc[mi][nt][1] + b1);
                *reinterpret_cast<float2*>(&outF[(size_t)(r0 + 8) * DIM + col]) =
                    make_float2(acc[mi][nt][2] + b0, acc[mi][nt][3] + b1);
            }
    } else {
        __nv_bfloat16* oh = outH + (size_t)z * ASZ;
        __nv_bfloat16* ol = outL + (size_t)z * ASZ;
#pragma unroll
        for (int mi = 0; mi < 2; mi++)
#pragma unroll
            for (int nt = 0; nt < 8; nt++) {
                int col = bn + wn + nt * 8 + tg * 2;
                float b0 = __ldg(&bias[col]), b1 = __ldg(&bias[col + 1]);
                int r0 = bm + wm + mi * 16 + g;
                uint32_t hi, lo;
                split2(acc[mi][nt][0] + b0, acc[mi][nt][1] + b1, hi, lo);
                *reinterpret_cast<uint32_t*>(oh + (size_t)r0 * DIM + col) = hi;
                *reinterpret_cast<uint32_t*>(ol + (size_t)r0 * DIM + col) = lo;
                split2(acc[mi][nt][2] + b0, acc[mi][nt][3] + b1, hi, lo);
                *reinterpret_cast<uint32_t*>(oh + (size_t)(r0 + 8) * DIM + col) = hi;
                *reinterpret_cast<uint32_t*>(ol + (size_t)(r0 + 8) * DIM + col) = lo;
            }
    }
}

// ---------------------------------------------------------------------------
// HMMA flash attention, split-bf16, causal, double-buffered KV prefetch.
// CTA: 128 q-rows x 8 warps, KV tile = 64 keys. V via ldmatrix.trans.
// ---------------------------------------------------------------------------
#define AB_ROWB 144
#define S_QH 0
#define S_QL 18432
#define KV0  36864
#define KV_STAGE 36864          // KH 9216 | KL 9216 | VH 9216 | VL 9216
#define ATTN_SMEM (KV0 + 2 * KV_STAGE)

__global__ __launch_bounds__(256, 1) void attn_mma(
    const __nv_bfloat16* __restrict__ qh, const __nv_bfloat16* __restrict__ ql,
    const __nv_bfloat16* __restrict__ kh, const __nv_bfloat16* __restrict__ kl,
    const __nv_bfloat16* __restrict__ vh, const __nv_bfloat16* __restrict__ vl,
    __nv_bfloat16* __restrict__ aoh, __nv_bfloat16* __restrict__ aol)
{
    extern __shared__ char smem[];
    const uint32_t sb = smem_u32(smem);
    const int tid = threadIdx.x, lane = tid & 31, warp = tid >> 5;
    const int g = lane >> 2, tg = lane & 3;
    const int blk = blockIdx.x, h = blockIdx.y, b = blockIdx.z;
    const int qbase = blk * 128;
    const int wq = warp * 16;
    const int hc = h * HD;

    const int aRow = lane & 15, aOff = (lane >> 4) * 16;
    const int bRow = ((lane >> 4) & 1) * 8 + (lane & 7);
    const int bOff = ((lane >> 3) & 1) * 16;
    const int vRow = (lane & 7) + ((lane >> 3) & 1) * 8;   // key within tile
    const int vCol = ((lane >> 4) & 1) * 16;               // dim byte offset

    // ---- KV prefetch helper ----
    auto prefetch_kv = [&](int j, int st) {
        const uint32_t so = sb + KV0 + st * KV_STAGE;
        for (int i = tid; i < 512; i += 256) {
            int r = i >> 3; int seg = (i & 7) * 16;
            uint32_t d = (uint32_t)r * AB_ROWB + seg;
            size_t gofs = ((size_t)(b * SEQ + j * 64 + r) * DIM + hc) * 2 + seg;
            cpa16(so + d,          (const char*)kh + gofs);
            cpa16(so + 9216 + d,   (const char*)kl + gofs);
            cpa16(so + 18432 + d,  (const char*)vh + gofs);
            cpa16(so + 27648 + d,  (const char*)vl + gofs);
        }
    };

    // ---- load Q tile (128 x 64) hi/lo + KV tile 0 ----
    for (int i = tid; i < 1024; i += 256) {
        int r = i >> 3; int seg = (i & 7) * 16;
        uint32_t d = (uint32_t)r * AB_ROWB + seg;
        size_t gofs = ((size_t)(b * SEQ + qbase + r) * DIM + hc) * 2 + seg;
        cpa16(sb + S_QH + d, (const char*)qh + gofs);
        cpa16(sb + S_QL + d, (const char*)ql + gofs);
    }
    prefetch_kv(0, 0);
    asm volatile("cp.async.commit_group;" ::: "memory");
    asm volatile("cp.async.wait_group 0;" ::: "memory");
    __syncthreads();

    const uint32_t raBase = (uint32_t)(wq + aRow) * AB_ROWB + aOff;
    uint32_t qfh[4][4], qfl[4][4];
#pragma unroll
    for (int ks = 0; ks < 4; ks++) {
        ldsm_x4(qfh[ks], sb + S_QH + raBase + ks * 32);
        ldsm_x4(qfl[ks], sb + S_QL + raBase + ks * 32);
    }

    float m0 = -1e30f, m1 = -1e30f, l0 = 0.f, l1 = 0.f;
    float oacc[8][4];
#pragma unroll
    for (int nt = 0; nt < 8; nt++)
#pragma unroll
        for (int q2 = 0; q2 < 4; q2++) oacc[nt][q2] = 0.f;

    const int jmax = 2 * blk + 1;
    for (int j = 0; j <= jmax; j++) {
        if (j + 1 <= jmax) {
            prefetch_kv(j + 1, (j + 1) & 1);
            asm volatile("cp.async.commit_group;" ::: "memory");
            asm volatile("cp.async.wait_group 1;" ::: "memory");
        } else {
            asm volatile("cp.async.wait_group 0;" ::: "memory");
        }
        __syncthreads();

        const uint32_t kvb = sb + KV0 + (j & 1) * KV_STAGE;
        const uint32_t sKH = kvb, sKL = kvb + 9216;
        const uint32_t sVH = kvb + 18432, sVL = kvb + 27648;

        if (qbase + wq + 15 >= j * 64) {     // warp-uniform
            // ---- S = Q @ K^T ----
            float sc[8][4];
#pragma unroll
            for (int nt = 0; nt < 8; nt++)
#pragma unroll
                for (int q2 = 0; q2 < 4; q2++) sc[nt][q2] = 0.f;
#pragma unroll
            for (int ks = 0; ks < 4; ks++) {
#pragma unroll
                for (int np = 0; np < 4; np++) {
                    uint32_t rb = (uint32_t)(np * 16 + bRow) * AB_ROWB + ks * 32 + bOff;
                    uint32_t bh4[4], bl4[4];
                    ldsm_x4(bh4, sKH + rb);
                    ldsm_x4(bl4, sKL + rb);
#pragma unroll
                    for (int sub = 0; sub < 2; sub++) {
                        mma_bf16(sc[np * 2 + sub], qfh[ks], bh4[2 * sub], bh4[2 * sub + 1]);
                        mma_bf16(sc[np * 2 + sub], qfh[ks], bl4[2 * sub], bl4[2 * sub + 1]);
                        mma_bf16(sc[np * 2 + sub], qfl[ks], bh4[2 * sub], bh4[2 * sub + 1]);
                    }
                }
            }

            // ---- scale + causal mask ----
            const int row0 = qbase + wq + g, row1 = row0 + 8;
#pragma unroll
            for (int nt = 0; nt < 8; nt++) {
                int kc = j * 64 + nt * 8 + 2 * tg;
                sc[nt][0] = (kc     <= row0) ? sc[nt][0] * 0.125f : -1e30f;
                sc[nt][1] = (kc + 1 <= row0) ? sc[nt][1] * 0.125f : -1e30f;
                sc[nt][2] = (kc     <= row1) ? sc[nt][2] * 0.125f : -1e30f;
                sc[nt][3] = (kc + 1 <= row1) ? sc[nt][3] * 0.125f : -1e30f;
            }

            // ---- online softmax ----
            float rm0 = -1e30f, rm1 = -1e30f;
#pragma unroll
            for (int nt = 0; nt < 8; nt++) {
                rm0 = fmaxf(rm0, fmaxf(sc[nt][0], sc[nt][1]));
                rm1 = fmaxf(rm1, fmaxf(sc[nt][2], sc[nt][3]));
            }
            rm0 = fmaxf(rm0, __shfl_xor_sync(0xffffffffu, rm0, 1));
            rm0 = fmaxf(rm0, __shfl_xor_sync(0xffffffffu, rm0, 2));
            rm1 = fmaxf(rm1, __shfl_xor_sync(0xffffffffu, rm1, 1));
            rm1 = fmaxf(rm1, __shfl_xor_sync(0xffffffffu, rm1, 2));
            float mn0 = fmaxf(m0, rm0), mn1 = fmaxf(m1, rm1);
            float al0 = __expf(m0 - mn0), al1 = __expf(m1 - mn1);
            m0 = mn0; m1 = mn1;
            float rs0 = 0.f, rs1 = 0.f;
#pragma unroll
            for (int nt = 0; nt < 8; nt++) {
                sc[nt][0] = __expf(sc[nt][0] - mn0);
                sc[nt][1] = __expf(sc[nt][1] - mn0);
                sc[nt][2] = __expf(sc[nt][2] - mn1);
                sc[nt][3] = __expf(sc[nt][3] - mn1);
                rs0 += sc[nt][0] + sc[nt][1];
                rs1 += sc[nt][2] + sc[nt][3];
            }
            rs0 += __shfl_xor_sync(0xffffffffu, rs0, 1);
            rs0 += __shfl_xor_sync(0xffffffffu, rs0, 2);
            rs1 += __shfl_xor_sync(0xffffffffu, rs1, 1);
            rs1 += __shfl_xor_sync(0xffffffffu, rs1, 2);
            l0 = l0 * al0 + rs0;
            l1 = l1 * al1 + rs1;
#pragma unroll
            for (int nt = 0; nt < 8; nt++) {
                oacc[nt][0] *= al0; oacc[nt][1] *= al0;
                oacc[nt][2] *= al1; oacc[nt][3] *= al1;
            }

            // ---- O += P @ V  (V via trans ldmatrix from [key][dim]) ----
#pragma unroll
            for (int ks = 0; ks < 4; ks++) {
                uint32_t pah[4], pal[4];
                split2(sc[2 * ks][0],     sc[2 * ks][1],     pah[0], pal[0]);
                split2(sc[2 * ks][2],     sc[2 * ks][3],     pah[1], pal[1]);
                split2(sc[2 * ks + 1][0], sc[2 * ks + 1][1], pah[2], pal[2]);
                split2(sc[2 * ks + 1][2], sc[2 * ks + 1][3], pah[3], pal[3]);
                uint32_t vbase = (uint32_t)(ks * 16 + vRow) * AB_ROWB + vCol;
#pragma unroll
                for (int ng = 0; ng < 4; ng++) {
                    uint32_t vh4[4], vl4[4];
                    ldsm_x4_t(vh4, sVH + vbase + ng * 32);
                    ldsm_x4_t(vl4, sVL + vbase + ng * 32);
                    mma_bf16(oacc[2 * ng],     pah, vh4[0], vh4[1]);
                    mma_bf16(oacc[2 * ng],     pah, vl4[0], vl4[1]);
                    mma_bf16(oacc[2 * ng],     pal, vh4[0], vh4[1]);
                    mma_bf16(oacc[2 * ng + 1], pah, vh4[2], vh4[3]);
                    mma_bf16(oacc[2 * ng + 1], pah, vl4[2], vl4[3]);
                    mma_bf16(oacc[2 * ng + 1], pal, vh4[2], vh4[3]);
                }
            }
        }
        __syncthreads();
    }

    // ---- epilogue: write hi/lo bf16 directly ----
    const float inv0 = 1.f / l0, inv1 = 1.f / l1;
    const size_t row0g = (size_t)(b * SEQ + qbase + wq + g);
#pragma unroll
    for (int nt = 0; nt < 8; nt++) {
        int col = hc + nt * 8 + 2 * tg;
        uint32_t hi, lo;
        split2(oacc[nt][0] * inv0, oacc[nt][1] * inv0, hi, lo);
        *reinterpret_cast<uint32_t*>(aoh + row0g * DIM + col) = hi;
        *reinterpret_cast<uint32_t*>(aol + row0g * DIM + col) = lo;
        split2(oacc[nt][2] * inv1, oacc[nt][3] * inv1, hi, lo);
        *reinterpret_cast<uint32_t*>(aoh + (row0g + 8) * DIM + col) = hi;
        *reinterpret_cast<uint32_t*>(aol + (row0g + 8) * DIM + col) = lo;
    }
}

// ---------------------------------------------------------------------------
extern "C" void kernel_launch(void* const* d_in, const int* in_sizes, int n_in,
                              void* d_out, int out_size)
{
    (void)in_sizes; (void)n_in; (void)out_size;
    const float* Q  = (const float*)d_in[0];
    const float* K  = (const float*)d_in[1];
    const float* V  = (const float*)d_in[2];
    const float* Wq = (const float*)d_in[4];
    const float* bq = (const float*)d_in[5];
    const float* Wk = (const float*)d_in[6];
    const float* bk = (const float*)d_in[7];
    const float* Wv = (const float*)d_in[8];
    const float* bv = (const float*)d_in[9];
    const float* Wo = (const float*)d_in[10];
    const float* bo = (const float*)d_in[11];

    __nv_bfloat16 *inh, *inl, *pwh, *pwl, *oh, *ol, *aoh, *aol;
    cudaGetSymbolAddress((void**)&inh, g_inh);
    cudaGetSymbolAddress((void**)&inl, g_inl);
    cudaGetSymbolAddress((void**)&pwh, g_pwh);
    cudaGetSymbolAddress((void**)&pwl, g_pwl);
    cudaGetSymbolAddress((void**)&oh,  g_oh);
    cudaGetSymbolAddress((void**)&ol,  g_ol);
    cudaGetSymbolAddress((void**)&aoh, g_aoh);
    cudaGetSymbolAddress((void**)&aol, g_aol);

    cudaFuncSetAttribute(gemm_mma,
                         cudaFuncAttributeMaxDynamicSharedMemorySize, GEMM_SMEM);
    cudaFuncSetAttribute(attn_mma,
                         cudaFuncAttributeMaxDynamicSharedMemorySize, ATTN_SMEM);

    // 1) split inputs (Q,K,V) and weights (Wq,Wk,Wv,Wo)
    split_in3<<<dim3(ASZ / 4 / 256, 3), 256>>>(Q, K, V, inh, inl);
    split_w4<<<dim3(WSZ / 4 / 256, 4), 256>>>(Wq, Wk, Wv, Wo, pwh, pwl);

    // 2) fused QKV projections (one launch, grid.z=3), bf16 hi/lo outputs
    gemm_mma<<<dim3(8, 32, 3), 256, GEMM_SMEM>>>(
        inh, inl, pwh, pwl, bq, bk, bv, oh, ol, nullptr);

    // 3) attention (HMMA, split-bf16), bf16 hi/lo output
    attn_mma<<<dim3(SEQ / 128, NH, BATCH), 256, ATTN_SMEM>>>(
        oh, ol, oh + ASZ, ol + ASZ, oh + 2 * (size_t)ASZ, ol + 2 * (size_t)ASZ,
        aoh, aol);

    // 4) output projection -> fp32 d_out
    gemm_mma<<<dim3(8, 32, 1), 256, GEMM_SMEM>>>(
        aoh, aol, pwh + 3 * (size_t)WSZ, pwl + 3 * (size_t)WSZ,
        bo, nullptr, nullptr, nullptr, nullptr, (float*)d_out);
}

// round 6
// speedup vs baseline: 3.1020x; 1.0286x over previous
#include <cuda_runtime.h>
#include <cuda_bf16.h>
#include <cstdint>

// Problem constants
#define BATCH 2
#define SEQ   2048
#define DIM   1024
#define NH    16
#define HD    64
#define MROWS (BATCH * SEQ)   // 4096
#define ASZ   (MROWS * DIM)   // 4M elements
#define WSZ   (DIM * DIM)     // 1M elements

// ---------------------------------------------------------------------------
// Scratch (__device__ globals; allocation-free rule)
// ---------------------------------------------------------------------------
__device__ __nv_bfloat16 g_inh[3 * ASZ], g_inl[3 * ASZ];   // split inputs Q,K,V
__device__ __nv_bfloat16 g_pwh[4 * WSZ], g_pwl[4 * WSZ];   // split weights
__device__ __nv_bfloat16 g_oh[3 * ASZ],  g_ol[3 * ASZ];    // projected q,k,v hi/lo
__device__ __nv_bfloat16 g_aoh[ASZ],     g_aol[ASZ];       // attention out hi/lo

// ---------------------------------------------------------------------------
// helpers
// ---------------------------------------------------------------------------
__device__ __forceinline__ uint32_t smem_u32(const void* p) {
    uint32_t a;
    asm("{ .reg .u64 t; cvta.to.shared.u64 t, %1; cvt.u32.u64 %0, t; }"
        : "=r"(a) : "l"(p));
    return a;
}

__device__ __forceinline__ void cpa16(uint32_t s, const void* g) {
    asm volatile("cp.async.cg.shared.global [%0], [%1], 16;" :: "r"(s), "l"(g));
}

__device__ __forceinline__ void ldsm_x4(uint32_t (&r)[4], uint32_t addr) {
    asm volatile("ldmatrix.sync.aligned.m8n8.x4.shared.b16 {%0,%1,%2,%3}, [%4];"
        : "=r"(r[0]), "=r"(r[1]), "=r"(r[2]), "=r"(r[3]) : "r"(addr));
}

__device__ __forceinline__ void ldsm_x4_t(uint32_t (&r)[4], uint32_t addr) {
    asm volatile("ldmatrix.sync.aligned.m8n8.x4.trans.shared.b16 {%0,%1,%2,%3}, [%4];"
        : "=r"(r[0]), "=r"(r[1]), "=r"(r[2]), "=r"(r[3]) : "r"(addr));
}

__device__ __forceinline__ void mma_bf16(float (&c)[4],
                                         const uint32_t (&a)[4],
                                         uint32_t b0, uint32_t b1) {
    asm volatile(
        "mma.sync.aligned.m16n8k16.row.col.f32.bf16.bf16.f32 "
        "{%0,%1,%2,%3}, {%4,%5,%6,%7}, {%8,%9}, {%0,%1,%2,%3};"
        : "+f"(c[0]), "+f"(c[1]), "+f"(c[2]), "+f"(c[3])
        : "r"(a[0]), "r"(a[1]), "r"(a[2]), "r"(a[3]), "r"(b0), "r"(b1));
}

__device__ __forceinline__ void split2(float a, float b, uint32_t& hi, uint32_t& lo) {
    __nv_bfloat162 h2 = __floats2bfloat162_rn(a, b);
    float ax = __bfloat162float(h2.x), bx = __bfloat162float(h2.y);
    __nv_bfloat162 l2 = __floats2bfloat162_rn(a - ax, b - bx);
    hi = *reinterpret_cast<uint32_t*>(&h2);
    lo = *reinterpret_cast<uint32_t*>(&l2);
}

// ---------------------------------------------------------------------------
// fp32 -> bf16 hi/lo splits (batched over planes)
// ---------------------------------------------------------------------------
__global__ __launch_bounds__(256) void split_in3(
    const float* __restrict__ a, const float* __restrict__ b,
    const float* __restrict__ c, __nv_bfloat16* __restrict__ h,
    __nv_bfloat16* __restrict__ l)
{
    const int plane = blockIdx.y;
    const float* src = plane == 0 ? a : (plane == 1 ? b : c);
    int i = blockIdx.x * 256 + threadIdx.x;          // float4 index
    float4 v = reinterpret_cast<const float4*>(src)[i];
    uint32_t h0, l0, h1, l1;
    split2(v.x, v.y, h0, l0);
    split2(v.z, v.w, h1, l1);
    uint32_t* ph = reinterpret_cast<uint32_t*>(h + (size_t)plane * ASZ);
    uint32_t* pl = reinterpret_cast<uint32_t*>(l + (size_t)plane * ASZ);
    ph[i * 2] = h0; ph[i * 2 + 1] = h1;
    pl[i * 2] = l0; pl[i * 2 + 1] = l1;
}

__global__ __launch_bounds__(256) void split_w4(
    const float* __restrict__ a, const float* __restrict__ b,
    const float* __restrict__ c, const float* __restrict__ d,
    __nv_bfloat16* __restrict__ h, __nv_bfloat16* __restrict__ l)
{
    const int plane = blockIdx.y;
    const float* src = plane == 0 ? a : (plane == 1 ? b : (plane == 2 ? c : d));
    int i = blockIdx.x * 256 + threadIdx.x;
    float4 v = reinterpret_cast<const float4*>(src)[i];
    uint32_t h0, l0, h1, l1;
    split2(v.x, v.y, h0, l0);
    split2(v.z, v.w, h1, l1);
    uint32_t* ph = reinterpret_cast<uint32_t*>(h + (size_t)plane * WSZ);
    uint32_t* pl = reinterpret_cast<uint32_t*>(l + (size_t)plane * WSZ);
    ph[i * 2] = h0; ph[i * 2 + 1] = h1;
    pl[i * 2] = l0; pl[i * 2 + 1] = l1;
}

// ---------------------------------------------------------------------------
// HMMA split-bf16 GEMM: C[4096,1024] = A @ W^T + bias,  grid.z selects plane.
// BM=128, BN=128, BK=32, 256 threads (8 warps, 4x2), warp tile 32x64.
// __launch_bounds__(256,2): 2 CTAs/SM (regs<=128, 2x80KB smem).
// ---------------------------------------------------------------------------
#define BKC        32
#define ROWB       80
#define BUF_B      (128 * ROWB)
#define STAGE_B    (4 * BUF_B)
#define GEMM_SMEM  (2 * STAGE_B)

__global__ __launch_bounds__(256, 2) void gemm_mma(
    const __nv_bfloat16* __restrict__ Ah, const __nv_bfloat16* __restrict__ Al,
    const __nv_bfloat16* __restrict__ Wh, const __nv_bfloat16* __restrict__ Wl,
    const float* __restrict__ bias0, const float* __restrict__ bias1,
    const float* __restrict__ bias2,
    __nv_bfloat16* __restrict__ outH, __nv_bfloat16* __restrict__ outL,
    float* __restrict__ outF)
{
    extern __shared__ char smem[];
    const uint32_t sb = smem_u32(smem);
    const int tid  = threadIdx.x;
    const int lane = tid & 31;
    const int warp = tid >> 5;
    const int wm = (warp >> 1) * 32;
    const int wn = (warp & 1) * 64;
    const int bm = blockIdx.y * 128;
    const int bn = blockIdx.x * 128;
    const int z  = blockIdx.z;
    const float* bias = z == 0 ? bias0 : (z == 1 ? bias1 : bias2);

    const __nv_bfloat16* gsrc[4] = {
        Ah + (size_t)z * ASZ + (size_t)bm * DIM,
        Al + (size_t)z * ASZ + (size_t)bm * DIM,
        Wh + (size_t)z * WSZ + (size_t)bn * DIM,
        Wl + (size_t)z * WSZ + (size_t)bn * DIM };

    float acc[2][8][4];
#pragma unroll
    for (int i = 0; i < 2; i++)
#pragma unroll
        for (int j = 0; j < 8; j++)
#pragma unroll
            for (int q = 0; q < 4; q++) acc[i][j][q] = 0.f;

    const int lrow = tid >> 2;
    const int lseg = (tid & 3) * 16;
    auto load_stage = [&](int ck, int st) {
        const uint32_t so = sb + st * STAGE_B;
        const size_t kb = (size_t)ck * BKC;
#pragma unroll
        for (int buf = 0; buf < 4; buf++) {
            const char* g = (const char*)(gsrc[buf] + kb);
            uint32_t s = so + buf * BUF_B;
#pragma unroll
            for (int half = 0; half < 2; half++) {
                int r = lrow + half * 64;
                cpa16(s + r * ROWB + lseg, g + (size_t)r * (DIM * 2) + lseg);
            }
        }
    };

    const int aRow = lane & 15;
    const int aOff = (lane >> 4) * 16;
    const int bRow = ((lane >> 4) & 1) * 8 + (lane & 7);
    const int bOff = ((lane >> 3) & 1) * 16;

    load_stage(0, 0);
    asm volatile("cp.async.commit_group;" ::: "memory");

    for (int ck = 0; ck < DIM / BKC; ck++) {
        if (ck + 1 < DIM / BKC) {
            load_stage(ck + 1, (ck + 1) & 1);
            asm volatile("cp.async.commit_group;" ::: "memory");
            asm volatile("cp.async.wait_group 1;" ::: "memory");
        } else {
            asm volatile("cp.async.wait_group 0;" ::: "memory");
        }
        __syncthreads();

        const uint32_t so = sb + (ck & 1) * STAGE_B;
        const uint32_t sAh = so;
        const uint32_t sAl = so + BUF_B;
        const uint32_t sBh = so + 2 * BUF_B;
        const uint32_t sBl = so + 3 * BUF_B;

#pragma unroll
        for (int ks = 0; ks < 2; ks++) {
            const int koff = ks * 32;
            uint32_t ah[2][4], al[2][4];
#pragma unroll
            for (int mi = 0; mi < 2; mi++) {
                uint32_t ra = (wm + mi * 16 + aRow) * ROWB + koff + aOff;
                ldsm_x4(ah[mi], sAh + ra);
                ldsm_x4(al[mi], sAl + ra);
            }
#pragma unroll
            for (int np = 0; np < 4; np++) {
                uint32_t rb = (wn + np * 16 + bRow) * ROWB + koff + bOff;
                uint32_t bh[4], bl[4];
                ldsm_x4(bh, sBh + rb);
                ldsm_x4(bl, sBl + rb);
#pragma unroll
                for (int sub = 0; sub < 2; sub++) {
                    uint32_t bh0 = bh[2 * sub], bh1 = bh[2 * sub + 1];
                    uint32_t bl0 = bl[2 * sub], bl1 = bl[2 * sub + 1];
#pragma unroll
                    for (int mi = 0; mi < 2; mi++) {
                        mma_bf16(acc[mi][np * 2 + sub], ah[mi], bh0, bh1);
                        mma_bf16(acc[mi][np * 2 + sub], ah[mi], bl0, bl1);
                        mma_bf16(acc[mi][np * 2 + sub], al[mi], bh0, bh1);
                    }
                }
            }
        }
        __syncthreads();
    }

    const int g  = lane >> 2;
    const int tg = lane & 3;
    if (outF) {
#pragma unroll
        for (int mi = 0; mi < 2; mi++)
#pragma unroll
            for (int nt = 0; nt < 8; nt++) {
                int col = bn + wn + nt * 8 + tg * 2;
                float b0 = __ldg(&bias[col]), b1 = __ldg(&bias[col + 1]);
                int r0 = bm + wm + mi * 16 + g;
                *reinterpret_cast<float2*>(&outF[(size_t)r0 * DIM + col]) =
                    make_float2(acc[mi][nt][0] + b0, acc[mi][nt][1] + b1);
                *reinterpret_cast<float2*>(&outF[(size_t)(r0 + 8) * DIM + col]) =
                    make_float2(acc[mi][nt][2] + b0, acc[mi][nt][3] + b1);
            }
    } else {
        __nv_bfloat16* oh = outH + (size_t)z * ASZ;
        __nv_bfloat16* ol = outL + (size_t)z * ASZ;
#pragma unroll
        for (int mi = 0; mi < 2; mi++)
#pragma unroll
            for (int nt = 0; nt < 8; nt++) {
                int col = bn + wn + nt * 8 + tg * 2;
                float b0 = __ldg(&bias[col]), b1 = __ldg(&bias[col + 1]);
                int r0 = bm + wm + mi * 16 + g;
                uint32_t hi, lo;
                split2(acc[mi][nt][0] + b0, acc[mi][nt][1] + b1, hi, lo);
                *reinterpret_cast<uint32_t*>(oh + (size_t)r0 * DIM + col) = hi;
                *reinterpret_cast<uint32_t*>(ol + (size_t)r0 * DIM + col) = lo;
                split2(acc[mi][nt][2] + b0, acc[mi][nt][3] + b1, hi, lo);
                *reinterpret_cast<uint32_t*>(oh + (size_t)(r0 + 8) * DIM + col) = hi;
                *reinterpret_cast<uint32_t*>(ol + (size_t)(r0 + 8) * DIM + col) = lo;
            }
    }
}

// ---------------------------------------------------------------------------
// HMMA flash attention, split-bf16, causal, double-buffered KV prefetch.
// CTA: 128 q-rows x 8 warps, KV tile = 64 keys. V via ldmatrix.trans.
// __launch_bounds__(256,2): 2 CTAs/SM (regs<=128; Q frags reloaded per tile).
// ---------------------------------------------------------------------------
#define AB_ROWB 144
#define S_QH 0
#define S_QL 18432
#define KV0  36864
#define KV_STAGE 36864          // KH 9216 | KL 9216 | VH 9216 | VL 9216
#define ATTN_SMEM (KV0 + 2 * KV_STAGE)

__global__ __launch_bounds__(256, 2) void attn_mma(
    const __nv_bfloat16* __restrict__ qh, const __nv_bfloat16* __restrict__ ql,
    const __nv_bfloat16* __restrict__ kh, const __nv_bfloat16* __restrict__ kl,
    const __nv_bfloat16* __restrict__ vh, const __nv_bfloat16* __restrict__ vl,
    __nv_bfloat16* __restrict__ aoh, __nv_bfloat16* __restrict__ aol)
{
    extern __shared__ char smem[];
    const uint32_t sb = smem_u32(smem);
    const int tid = threadIdx.x, lane = tid & 31, warp = tid >> 5;
    const int g = lane >> 2, tg = lane & 3;
    const int blk = blockIdx.x, h = blockIdx.y, b = blockIdx.z;
    const int qbase = blk * 128;
    const int wq = warp * 16;
    const int hc = h * HD;

    const int aRow = lane & 15, aOff = (lane >> 4) * 16;
    const int bRow = ((lane >> 4) & 1) * 8 + (lane & 7);
    const int bOff = ((lane >> 3) & 1) * 16;
    const int vRow = (lane & 7) + ((lane >> 3) & 1) * 8;   // key within tile
    const int vCol = ((lane >> 4) & 1) * 16;               // dim byte offset

    // ---- KV prefetch helper ----
    auto prefetch_kv = [&](int j, int st) {
        const uint32_t so = sb + KV0 + st * KV_STAGE;
        for (int i = tid; i < 512; i += 256) {
            int r = i >> 3; int seg = (i & 7) * 16;
            uint32_t d = (uint32_t)r * AB_ROWB + seg;
            size_t gofs = ((size_t)(b * SEQ + j * 64 + r) * DIM + hc) * 2 + seg;
            cpa16(so + d,          (const char*)kh + gofs);
            cpa16(so + 9216 + d,   (const char*)kl + gofs);
            cpa16(so + 18432 + d,  (const char*)vh + gofs);
            cpa16(so + 27648 + d,  (const char*)vl + gofs);
        }
    };

    // ---- load Q tile (128 x 64) hi/lo + KV tile 0 ----
    for (int i = tid; i < 1024; i += 256) {
        int r = i >> 3; int seg = (i & 7) * 16;
        uint32_t d = (uint32_t)r * AB_ROWB + seg;
        size_t gofs = ((size_t)(b * SEQ + qbase + r) * DIM + hc) * 2 + seg;
        cpa16(sb + S_QH + d, (const char*)qh + gofs);
        cpa16(sb + S_QL + d, (const char*)ql + gofs);
    }
    prefetch_kv(0, 0);
    asm volatile("cp.async.commit_group;" ::: "memory");
    asm volatile("cp.async.wait_group 0;" ::: "memory");
    __syncthreads();

    const uint32_t raBase = (uint32_t)(wq + aRow) * AB_ROWB + aOff;

    float m0 = -1e30f, m1 = -1e30f, l0 = 0.f, l1 = 0.f;
    float oacc[8][4];
#pragma unroll
    for (int nt = 0; nt < 8; nt++)
#pragma unroll
        for (int q2 = 0; q2 < 4; q2++) oacc[nt][q2] = 0.f;

    const int jmax = 2 * blk + 1;
    for (int j = 0; j <= jmax; j++) {
        if (j + 1 <= jmax) {
            prefetch_kv(j + 1, (j + 1) & 1);
            asm volatile("cp.async.commit_group;" ::: "memory");
            asm volatile("cp.async.wait_group 1;" ::: "memory");
        } else {
            asm volatile("cp.async.wait_group 0;" ::: "memory");
        }
        __syncthreads();

        const uint32_t kvb = sb + KV0 + (j & 1) * KV_STAGE;
        const uint32_t sKH = kvb, sKL = kvb + 9216;
        const uint32_t sVH = kvb + 18432, sVL = kvb + 27648;

        if (qbase + wq + 15 >= j * 64) {     // warp-uniform
            // ---- S = Q @ K^T (Q frags reloaded per tile to cap regs) ----
            float sc[8][4];
#pragma unroll
            for (int nt = 0; nt < 8; nt++)
#pragma unroll
                for (int q2 = 0; q2 < 4; q2++) sc[nt][q2] = 0.f;
#pragma unroll
            for (int ks = 0; ks < 4; ks++) {
                uint32_t qfh[4], qfl[4];
                ldsm_x4(qfh, sb + S_QH + raBase + ks * 32);
                ldsm_x4(qfl, sb + S_QL + raBase + ks * 32);
#pragma unroll
                for (int np = 0; np < 4; np++) {
                    uint32_t rb = (uint32_t)(np * 16 + bRow) * AB_ROWB + ks * 32 + bOff;
                    uint32_t bh4[4], bl4[4];
                    ldsm_x4(bh4, sKH + rb);
                    ldsm_x4(bl4, sKL + rb);
#pragma unroll
                    for (int sub = 0; sub < 2; sub++) {
                        mma_bf16(sc[np * 2 + sub], qfh, bh4[2 * sub], bh4[2 * sub + 1]);
                        mma_bf16(sc[np * 2 + sub], qfh, bl4[2 * sub], bl4[2 * sub + 1]);
                        mma_bf16(sc[np * 2 + sub], qfl, bh4[2 * sub], bh4[2 * sub + 1]);
                    }
                }
            }

            // ---- scale + causal mask ----
            const int row0 = qbase + wq + g, row1 = row0 + 8;
#pragma unroll
            for (int nt = 0; nt < 8; nt++) {
                int kc = j * 64 + nt * 8 + 2 * tg;
                sc[nt][0] = (kc     <= row0) ? sc[nt][0] * 0.125f : -1e30f;
                sc[nt][1] = (kc + 1 <= row0) ? sc[nt][1] * 0.125f : -1e30f;
                sc[nt][2] = (kc     <= row1) ? sc[nt][2] * 0.125f : -1e30f;
                sc[nt][3] = (kc + 1 <= row1) ? sc[nt][3] * 0.125f : -1e30f;
            }

            // ---- online softmax ----
            float rm0 = -1e30f, rm1 = -1e30f;
#pragma unroll
            for (int nt = 0; nt < 8; nt++) {
                rm0 = fmaxf(rm0, fmaxf(sc[nt][0], sc[nt][1]));
                rm1 = fmaxf(rm1, fmaxf(sc[nt][2], sc[nt][3]));
            }
            rm0 = fmaxf(rm0, __shfl_xor_sync(0xffffffffu, rm0, 1));
            rm0 = fmaxf(rm0, __shfl_xor_sync(0xffffffffu, rm0, 2));
            rm1 = fmaxf(rm1, __shfl_xor_sync(0xffffffffu, rm1, 1));
            rm1 = fmaxf(rm1, __shfl_xor_sync(0xffffffffu, rm1, 2));
            float mn0 = fmaxf(m0, rm0), mn1 = fmaxf(m1, rm1);
            float al0 = __expf(m0 - mn0), al1 = __expf(m1 - mn1);
            m0 = mn0; m1 = mn1;
            float rs0 = 0.f, rs1 = 0.f;
#pragma unroll
            for (int nt = 0; nt < 8; nt++) {
                sc[nt][0] = __expf(sc[nt][0] - mn0);
                sc[nt][1] = __expf(sc[nt][1] - mn0);
                sc[nt][2] = __expf(sc[nt][2] - mn1);
                sc[nt][3] = __expf(sc[nt][3] - mn1);
                rs0 += sc[nt][0] + sc[nt][1];
                rs1 += sc[nt][2] + sc[nt][3];
            }
            rs0 += __shfl_xor_sync(0xffffffffu, rs0, 1);
            rs0 += __shfl_xor_sync(0xffffffffu, rs0, 2);
            rs1 += __shfl_xor_sync(0xffffffffu, rs1, 1);
            rs1 += __shfl_xor_sync(0xffffffffu, rs1, 2);
            l0 = l0 * al0 + rs0;
            l1 = l1 * al1 + rs1;
#pragma unroll
            for (int nt = 0; nt < 8; nt++) {
                oacc[nt][0] *= al0; oacc[nt][1] *= al0;
                oacc[nt][2] *= al1; oacc[nt][3] *= al1;
            }

            // ---- O += P @ V  (V via trans ldmatrix from [key][dim]) ----
#pragma unroll
            for (int ks = 0; ks < 4; ks++) {
                uint32_t pah[4], pal[4];
                split2(sc[2 * ks][0],     sc[2 * ks][1],     pah[0], pal[0]);
                split2(sc[2 * ks][2],     sc[2 * ks][3],     pah[1], pal[1]);
                split2(sc[2 * ks + 1][0], sc[2 * ks + 1][1], pah[2], pal[2]);
                split2(sc[2 * ks + 1][2], sc[2 * ks + 1][3], pah[3], pal[3]);
                uint32_t vbase = (uint32_t)(ks * 16 + vRow) * AB_ROWB + vCol;
#pragma unroll
                for (int ng = 0; ng < 4; ng++) {
                    uint32_t vh4[4], vl4[4];
                    ldsm_x4_t(vh4, sVH + vbase + ng * 32);
                    ldsm_x4_t(vl4, sVL + vbase + ng * 32);
                    mma_bf16(oacc[2 * ng],     pah, vh4[0], vh4[1]);
                    mma_bf16(oacc[2 * ng],     pah, vl4[0], vl4[1]);
                    mma_bf16(oacc[2 * ng],     pal, vh4[0], vh4[1]);
                    mma_bf16(oacc[2 * ng + 1], pah, vh4[2], vh4[3]);
                    mma_bf16(oacc[2 * ng + 1], pah, vl4[2], vl4[3]);
                    mma_bf16(oacc[2 * ng + 1], pal, vh4[2], vh4[3]);
                }
            }
        }
        __syncthreads();
    }

    // ---- epilogue: write hi/lo bf16 directly ----
    const float inv0 = 1.f / l0, inv1 = 1.f / l1;
    const size_t row0g = (size_t)(b * SEQ + qbase + wq + g);
#pragma unroll
    for (int nt = 0; nt < 8; nt++) {
        int col = hc + nt * 8 + 2 * tg;
        uint32_t hi, lo;
        split2(oacc[nt][0] * inv0, oacc[nt][1] * inv0, hi, lo);
        *reinterpret_cast<uint32_t*>(aoh + row0g * DIM + col) = hi;
        *reinterpret_cast<uint32_t*>(aol + row0g * DIM + col) = lo;
        split2(oacc[nt][2] * inv1, oacc[nt][3] * inv1, hi, lo);
        *reinterpret_cast<uint32_t*>(aoh + (row0g + 8) * DIM + col) = hi;
        *reinterpret_cast<uint32_t*>(aol + (row0g + 8) * DIM + col) = lo;
    }
}

// ---------------------------------------------------------------------------
extern "C" void kernel_launch(void* const* d_in, const int* in_sizes, int n_in,
                              void* d_out, int out_size)
{
    (void)in_sizes; (void)n_in; (void)out_size;
    const float* Q  = (const float*)d_in[0];
    const float* K  = (const float*)d_in[1];
    const float* V  = (const float*)d_in[2];
    const float* Wq = (const float*)d_in[4];
    const float* bq = (const float*)d_in[5];
    const float* Wk = (const float*)d_in[6];
    const float* bk = (const float*)d_in[7];
    const float* Wv = (const float*)d_in[8];
    const float* bv = (const float*)d_in[9];
    const float* Wo = (const float*)d_in[10];
    const float* bo = (const float*)d_in[11];

    __nv_bfloat16 *inh, *inl, *pwh, *pwl, *oh, *ol, *aoh, *aol;
    cudaGetSymbolAddress((void**)&inh, g_inh);
    cudaGetSymbolAddress((void**)&inl, g_inl);
    cudaGetSymbolAddress((void**)&pwh, g_pwh);
    cudaGetSymbolAddress((void**)&pwl, g_pwl);
    cudaGetSymbolAddress((void**)&oh,  g_oh);
    cudaGetSymbolAddress((void**)&ol,  g_ol);
    cudaGetSymbolAddress((void**)&aoh, g_aoh);
    cudaGetSymbolAddress((void**)&aol, g_aol);

    cudaFuncSetAttribute(gemm_mma,
                         cudaFuncAttributeMaxDynamicSharedMemorySize, GEMM_SMEM);
    cudaFuncSetAttribute(attn_mma,
                         cudaFuncAttributeMaxDynamicSharedMemorySize, ATTN_SMEM);

    // 1) split inputs (Q,K,V) and weights (Wq,Wk,Wv,Wo)
    split_in3<<<dim3(ASZ / 4 / 256, 3), 256>>>(Q, K, V, inh, inl);
    split_w4<<<dim3(WSZ / 4 / 256, 4), 256>>>(Wq, Wk, Wv, Wo, pwh, pwl);

    // 2) fused QKV projections (one launch, grid.z=3), bf16 hi/lo outputs
    gemm_mma<<<dim3(8, 32, 3), 256, GEMM_SMEM>>>(
        inh, inl, pwh, pwl, bq, bk, bv, oh, ol, nullptr);

    // 3) attention (HMMA, split-bf16), bf16 hi/lo output
    attn_mma<<<dim3(SEQ / 128, NH, BATCH), 256, ATTN_SMEM>>>(
        oh, ol, oh + ASZ, ol + ASZ, oh + 2 * (size_t)ASZ, ol + 2 * (size_t)ASZ,
        aoh, aol);

    // 4) output projection -> fp32 d_out
    gemm_mma<<<dim3(8, 32, 1), 256, GEMM_SMEM>>>(
        aoh, aol, pwh + 3 * (size_t)WSZ, pwl + 3 * (size_t)WSZ,
        bo, nullptr, nullptr, nullptr, nullptr, (float*)d_out);
}

// round 7
// speedup vs baseline: 3.1770x; 1.0242x over previous
#include <cuda_runtime.h>
#include <cuda_bf16.h>
#include <cstdint>

// Problem constants
#define BATCH 2
#define SEQ   2048
#define DIM   1024
#define NH    16
#define HD    64
#define MROWS (BATCH * SEQ)   // 4096
#define ASZ   (MROWS * DIM)   // 4M elements
#define WSZ   (DIM * DIM)     // 1M elements

// ---------------------------------------------------------------------------
// Scratch (__device__ globals; allocation-free rule)
// ---------------------------------------------------------------------------
__device__ __nv_bfloat16 g_inh[3 * ASZ], g_inl[3 * ASZ];   // split inputs Q,K,V
__device__ __nv_bfloat16 g_pwh[4 * WSZ], g_pwl[4 * WSZ];   // split weights
__device__ __nv_bfloat16 g_oh[3 * ASZ],  g_ol[3 * ASZ];    // projected q,k,v hi/lo
__device__ __nv_bfloat16 g_aoh[ASZ],     g_aol[ASZ];       // attention out hi/lo

// ---------------------------------------------------------------------------
// helpers
// ---------------------------------------------------------------------------
__device__ __forceinline__ uint32_t smem_u32(const void* p) {
    uint32_t a;
    asm("{ .reg .u64 t; cvta.to.shared.u64 t, %1; cvt.u32.u64 %0, t; }"
        : "=r"(a) : "l"(p));
    return a;
}

__device__ __forceinline__ void cpa16(uint32_t s, const void* g) {
    asm volatile("cp.async.cg.shared.global [%0], [%1], 16;" :: "r"(s), "l"(g));
}

__device__ __forceinline__ void ldsm_x4(uint32_t (&r)[4], uint32_t addr) {
    asm volatile("ldmatrix.sync.aligned.m8n8.x4.shared.b16 {%0,%1,%2,%3}, [%4];"
        : "=r"(r[0]), "=r"(r[1]), "=r"(r[2]), "=r"(r[3]) : "r"(addr));
}

__device__ __forceinline__ void ldsm_x4_t(uint32_t (&r)[4], uint32_t addr) {
    asm volatile("ldmatrix.sync.aligned.m8n8.x4.trans.shared.b16 {%0,%1,%2,%3}, [%4];"
        : "=r"(r[0]), "=r"(r[1]), "=r"(r[2]), "=r"(r[3]) : "r"(addr));
}

__device__ __forceinline__ void mma_bf16(float (&c)[4],
                                         const uint32_t (&a)[4],
                                         uint32_t b0, uint32_t b1) {
    asm volatile(
        "mma.sync.aligned.m16n8k16.row.col.f32.bf16.bf16.f32 "
        "{%0,%1,%2,%3}, {%4,%5,%6,%7}, {%8,%9}, {%0,%1,%2,%3};"
        : "+f"(c[0]), "+f"(c[1]), "+f"(c[2]), "+f"(c[3])
        : "r"(a[0]), "r"(a[1]), "r"(a[2]), "r"(a[3]), "r"(b0), "r"(b1));
}

__device__ __forceinline__ void split2(float a, float b, uint32_t& hi, uint32_t& lo) {
    __nv_bfloat162 h2 = __floats2bfloat162_rn(a, b);
    float ax = __bfloat162float(h2.x), bx = __bfloat162float(h2.y);
    __nv_bfloat162 l2 = __floats2bfloat162_rn(a - ax, b - bx);
    hi = *reinterpret_cast<uint32_t*>(&h2);
    lo = *reinterpret_cast<uint32_t*>(&l2);
}

// ---------------------------------------------------------------------------
// fp32 -> bf16 hi/lo splits (batched over planes)
// ---------------------------------------------------------------------------
__global__ __launch_bounds__(256) void split_in3(
    const float* __restrict__ a, const float* __restrict__ b,
    const float* __restrict__ c, __nv_bfloat16* __restrict__ h,
    __nv_bfloat16* __restrict__ l)
{
    const int plane = blockIdx.y;
    const float* src = plane == 0 ? a : (plane == 1 ? b : c);
    int i = blockIdx.x * 256 + threadIdx.x;          // float4 index
    float4 v = reinterpret_cast<const float4*>(src)[i];
    uint32_t h0, l0, h1, l1;
    split2(v.x, v.y, h0, l0);
    split2(v.z, v.w, h1, l1);
    uint32_t* ph = reinterpret_cast<uint32_t*>(h + (size_t)plane * ASZ);
    uint32_t* pl = reinterpret_cast<uint32_t*>(l + (size_t)plane * ASZ);
    ph[i * 2] = h0; ph[i * 2 + 1] = h1;
    pl[i * 2] = l0; pl[i * 2 + 1] = l1;
}

__global__ __launch_bounds__(256) void split_w4(
    const float* __restrict__ a, const float* __restrict__ b,
    const float* __restrict__ c, const float* __restrict__ d,
    __nv_bfloat16* __restrict__ h, __nv_bfloat16* __restrict__ l)
{
    const int plane = blockIdx.y;
    const float* src = plane == 0 ? a : (plane == 1 ? b : (plane == 2 ? c : d));
    int i = blockIdx.x * 256 + threadIdx.x;
    float4 v = reinterpret_cast<const float4*>(src)[i];
    uint32_t h0, l0, h1, l1;
    split2(v.x, v.y, h0, l0);
    split2(v.z, v.w, h1, l1);
    uint32_t* ph = reinterpret_cast<uint32_t*>(h + (size_t)plane * WSZ);
    uint32_t* pl = reinterpret_cast<uint32_t*>(l + (size_t)plane * WSZ);
    ph[i * 2] = h0; ph[i * 2 + 1] = h1;
    pl[i * 2] = l0; pl[i * 2 + 1] = l1;
}

// ---------------------------------------------------------------------------
// HMMA split-bf16 GEMM: C[4096,1024] = A @ W^T + bias,  grid.z selects plane.
// BM=128, BN=128, BK=32, 256 threads (8 warps, 4x2), warp tile 32x64.
// __launch_bounds__(256,2): 2 CTAs/SM. Term-major MMA order (chain spacing 4).
// ---------------------------------------------------------------------------
#define BKC        32
#define ROWB       80
#define BUF_B      (128 * ROWB)
#define STAGE_B    (4 * BUF_B)
#define GEMM_SMEM  (2 * STAGE_B)

__global__ __launch_bounds__(256, 2) void gemm_mma(
    const __nv_bfloat16* __restrict__ Ah, const __nv_bfloat16* __restrict__ Al,
    const __nv_bfloat16* __restrict__ Wh, const __nv_bfloat16* __restrict__ Wl,
    const float* __restrict__ bias0, const float* __restrict__ bias1,
    const float* __restrict__ bias2,
    __nv_bfloat16* __restrict__ outH, __nv_bfloat16* __restrict__ outL,
    float* __restrict__ outF)
{
    extern __shared__ char smem[];
    const uint32_t sb = smem_u32(smem);
    const int tid  = threadIdx.x;
    const int lane = tid & 31;
    const int warp = tid >> 5;
    const int wm = (warp >> 1) * 32;
    const int wn = (warp & 1) * 64;
    const int bm = blockIdx.y * 128;
    const int bn = blockIdx.x * 128;
    const int z  = blockIdx.z;
    const float* bias = z == 0 ? bias0 : (z == 1 ? bias1 : bias2);

    const __nv_bfloat16* gsrc[4] = {
        Ah + (size_t)z * ASZ + (size_t)bm * DIM,
        Al + (size_t)z * ASZ + (size_t)bm * DIM,
        Wh + (size_t)z * WSZ + (size_t)bn * DIM,
        Wl + (size_t)z * WSZ + (size_t)bn * DIM };

    float acc[2][8][4];
#pragma unroll
    for (int i = 0; i < 2; i++)
#pragma unroll
        for (int j = 0; j < 8; j++)
#pragma unroll
            for (int q = 0; q < 4; q++) acc[i][j][q] = 0.f;

    const int lrow = tid >> 2;
    const int lseg = (tid & 3) * 16;
    auto load_stage = [&](int ck, int st) {
        const uint32_t so = sb + st * STAGE_B;
        const size_t kb = (size_t)ck * BKC;
#pragma unroll
        for (int buf = 0; buf < 4; buf++) {
            const char* g = (const char*)(gsrc[buf] + kb);
            uint32_t s = so + buf * BUF_B;
#pragma unroll
            for (int half = 0; half < 2; half++) {
                int r = lrow + half * 64;
                cpa16(s + r * ROWB + lseg, g + (size_t)r * (DIM * 2) + lseg);
            }
        }
    };

    const int aRow = lane & 15;
    const int aOff = (lane >> 4) * 16;
    const int bRow = ((lane >> 4) & 1) * 8 + (lane & 7);
    const int bOff = ((lane >> 3) & 1) * 16;

    load_stage(0, 0);
    asm volatile("cp.async.commit_group;" ::: "memory");

    for (int ck = 0; ck < DIM / BKC; ck++) {
        if (ck + 1 < DIM / BKC) {
            load_stage(ck + 1, (ck + 1) & 1);
            asm volatile("cp.async.commit_group;" ::: "memory");
            asm volatile("cp.async.wait_group 1;" ::: "memory");
        } else {
            asm volatile("cp.async.wait_group 0;" ::: "memory");
        }
        __syncthreads();

        const uint32_t so = sb + (ck & 1) * STAGE_B;
        const uint32_t sAh = so;
        const uint32_t sAl = so + BUF_B;
        const uint32_t sBh = so + 2 * BUF_B;
        const uint32_t sBl = so + 3 * BUF_B;

#pragma unroll
        for (int ks = 0; ks < 2; ks++) {
            const int koff = ks * 32;
            uint32_t ah[2][4], al[2][4];
#pragma unroll
            for (int mi = 0; mi < 2; mi++) {
                uint32_t ra = (wm + mi * 16 + aRow) * ROWB + koff + aOff;
                ldsm_x4(ah[mi], sAh + ra);
                ldsm_x4(al[mi], sAl + ra);
            }
#pragma unroll
            for (int np = 0; np < 4; np++) {
                uint32_t rb = (wn + np * 16 + bRow) * ROWB + koff + bOff;
                uint32_t bh[4], bl[4];
                ldsm_x4(bh, sBh + rb);
                ldsm_x4(bl, sBl + rb);
                // term-major: 4 independent accs per term (chain spacing 4)
#pragma unroll
                for (int mi = 0; mi < 2; mi++) {
                    mma_bf16(acc[mi][np * 2 + 0], ah[mi], bh[0], bh[1]);
                    mma_bf16(acc[mi][np * 2 + 1], ah[mi], bh[2], bh[3]);
                }
#pragma unroll
                for (int mi = 0; mi < 2; mi++) {
                    mma_bf16(acc[mi][np * 2 + 0], ah[mi], bl[0], bl[1]);
                    mma_bf16(acc[mi][np * 2 + 1], ah[mi], bl[2], bl[3]);
                }
#pragma unroll
                for (int mi = 0; mi < 2; mi++) {
                    mma_bf16(acc[mi][np * 2 + 0], al[mi], bh[0], bh[1]);
                    mma_bf16(acc[mi][np * 2 + 1], al[mi], bh[2], bh[3]);
                }
            }
        }
        __syncthreads();
    }

    const int g  = lane >> 2;
    const int tg = lane & 3;
    if (outF) {
#pragma unroll
        for (int mi = 0; mi < 2; mi++)
#pragma unroll
            for (int nt = 0; nt < 8; nt++) {
                int col = bn + wn + nt * 8 + tg * 2;
                float b0 = __ldg(&bias[col]), b1 = __ldg(&bias[col + 1]);
                int r0 = bm + wm + mi * 16 + g;
                *reinterpret_cast<float2*>(&outF[(size_t)r0 * DIM + col]) =
                    make_float2(acc[mi][nt][0] + b0, acc[mi][nt][1] + b1);
                *reinterpret_cast<float2*>(&outF[(size_t)(r0 + 8) * DIM + col]) =
                    make_float2(acc[mi][nt][2] + b0, acc[mi][nt][3] + b1);
            }
    } else {
        __nv_bfloat16* oh = outH + (size_t)z * ASZ;
        __nv_bfloat16* ol = outL + (size_t)z * ASZ;
#pragma unroll
        for (int mi = 0; mi < 2; mi++)
#pragma unroll
            for (int nt = 0; nt < 8; nt++) {
                int col = bn + wn + nt * 8 + tg * 2;
                float b0 = __ldg(&bias[col]), b1 = __ldg(&bias[col + 1]);
                int r0 = bm + wm + mi * 16 + g;
                uint32_t hi, lo;
                split2(acc[mi][nt][0] + b0, acc[mi][nt][1] + b1, hi, lo);
                *reinterpret_cast<uint32_t*>(oh + (size_t)r0 * DIM + col) = hi;
                *reinterpret_cast<uint32_t*>(ol + (size_t)r0 * DIM + col) = lo;
                split2(acc[mi][nt][2] + b0, acc[mi][nt][3] + b1, hi, lo);
                *reinterpret_cast<uint32_t*>(oh + (size_t)(r0 + 8) * DIM + col) = hi;
                *reinterpret_cast<uint32_t*>(ol + (size_t)(r0 + 8) * DIM + col) = lo;
            }
    }
}

// ---------------------------------------------------------------------------
// HMMA flash attention, split-bf16, causal, 3-stage cp.async KV ring.
// CTA: 128 q-rows x 8 warps, KV tile = 64 keys. 1 CTA/SM, persistent Q frags.
// Term-major MMA issue order (chain spacing 8).
// ---------------------------------------------------------------------------
#define AB_ROWB 144
#define S_QH 0
#define S_QL 18432
#define KV0  36864
#define KV_STAGE 36864          // KH 9216 | KL 9216 | VH 9216 | VL 9216
#define ATTN_SMEM (KV0 + 3 * KV_STAGE)   // 147456

__global__ __launch_bounds__(256, 1) void attn_mma(
    const __nv_bfloat16* __restrict__ qh, const __nv_bfloat16* __restrict__ ql,
    const __nv_bfloat16* __restrict__ kh, const __nv_bfloat16* __restrict__ kl,
    const __nv_bfloat16* __restrict__ vh, const __nv_bfloat16* __restrict__ vl,
    __nv_bfloat16* __restrict__ aoh, __nv_bfloat16* __restrict__ aol)
{
    extern __shared__ char smem[];
    const uint32_t sb = smem_u32(smem);
    const int tid = threadIdx.x, lane = tid & 31, warp = tid >> 5;
    const int g = lane >> 2, tg = lane & 3;
    const int blk = blockIdx.x, h = blockIdx.y, b = blockIdx.z;
    const int qbase = blk * 128;
    const int wq = warp * 16;
    const int hc = h * HD;

    const int aRow = lane & 15, aOff = (lane >> 4) * 16;
    const int bRow = ((lane >> 4) & 1) * 8 + (lane & 7);
    const int bOff = ((lane >> 3) & 1) * 16;
    const int vRow = (lane & 7) + ((lane >> 3) & 1) * 8;   // key within tile
    const int vCol = ((lane >> 4) & 1) * 16;               // dim byte offset

    auto prefetch_kv = [&](int j) {
        const uint32_t so = sb + KV0 + (uint32_t)(j % 3) * KV_STAGE;
        for (int i = tid; i < 512; i += 256) {
            int r = i >> 3; int seg = (i & 7) * 16;
            uint32_t d = (uint32_t)r * AB_ROWB + seg;
            size_t gofs = ((size_t)(b * SEQ + j * 64 + r) * DIM + hc) * 2 + seg;
            cpa16(so + d,          (const char*)kh + gofs);
            cpa16(so + 9216 + d,   (const char*)kl + gofs);
            cpa16(so + 18432 + d,  (const char*)vh + gofs);
            cpa16(so + 27648 + d,  (const char*)vl + gofs);
        }
    };

    const int jmax = 2 * blk + 1;

    // group 0: Q tile + KV tile 0;  group 1: KV tile 1
    for (int i = tid; i < 1024; i += 256) {
        int r = i >> 3; int seg = (i & 7) * 16;
        uint32_t d = (uint32_t)r * AB_ROWB + seg;
        size_t gofs = ((size_t)(b * SEQ + qbase + r) * DIM + hc) * 2 + seg;
        cpa16(sb + S_QH + d, (const char*)qh + gofs);
        cpa16(sb + S_QL + d, (const char*)ql + gofs);
    }
    prefetch_kv(0);
    asm volatile("cp.async.commit_group;" ::: "memory");
    prefetch_kv(1);
    asm volatile("cp.async.commit_group;" ::: "memory");

    asm volatile("cp.async.wait_group 1;" ::: "memory");
    __syncthreads();

    const uint32_t raBase = (uint32_t)(wq + aRow) * AB_ROWB + aOff;
    uint32_t qfh[4][4], qfl[4][4];
#pragma unroll
    for (int ks = 0; ks < 4; ks++) {
        ldsm_x4(qfh[ks], sb + S_QH + raBase + ks * 32);
        ldsm_x4(qfl[ks], sb + S_QL + raBase + ks * 32);
    }

    float m0 = -1e30f, m1 = -1e30f, l0 = 0.f, l1 = 0.f;
    float oacc[8][4];
#pragma unroll
    for (int nt = 0; nt < 8; nt++)
#pragma unroll
        for (int q2 = 0; q2 < 4; q2++) oacc[nt][q2] = 0.f;

    for (int j = 0; j <= jmax; j++) {
        if (j + 2 <= jmax) {
            prefetch_kv(j + 2);
            asm volatile("cp.async.commit_group;" ::: "memory");
            asm volatile("cp.async.wait_group 2;" ::: "memory");
        } else if (j + 1 <= jmax) {
            asm volatile("cp.async.wait_group 1;" ::: "memory");
        } else {
            asm volatile("cp.async.wait_group 0;" ::: "memory");
        }
        __syncthreads();

        const uint32_t kvb = sb + KV0 + (uint32_t)(j % 3) * KV_STAGE;
        const uint32_t sKH = kvb, sKL = kvb + 9216;
        const uint32_t sVH = kvb + 18432, sVL = kvb + 27648;

        if (qbase + wq + 15 >= j * 64) {     // warp-uniform
            // ---- S = Q @ K^T, term-major issue ----
            float sc[8][4];
#pragma unroll
            for (int nt = 0; nt < 8; nt++)
#pragma unroll
                for (int q2 = 0; q2 < 4; q2++) sc[nt][q2] = 0.f;
#pragma unroll
            for (int ks = 0; ks < 4; ks++) {
                uint32_t bh4[4][4], bl4[4][4];
#pragma unroll
                for (int np = 0; np < 4; np++) {
                    uint32_t rb = (uint32_t)(np * 16 + bRow) * AB_ROWB + ks * 32 + bOff;
                    ldsm_x4(bh4[np], sKH + rb);
                    ldsm_x4(bl4[np], sKL + rb);
                }
                // 8 accs per term: chain spacing 8
#pragma unroll
                for (int np = 0; np < 4; np++) {
                    mma_bf16(sc[np * 2 + 0], qfh[ks], bh4[np][0], bh4[np][1]);
                    mma_bf16(sc[np * 2 + 1], qfh[ks], bh4[np][2], bh4[np][3]);
                }
#pragma unroll
                for (int np = 0; np < 4; np++) {
                    mma_bf16(sc[np * 2 + 0], qfh[ks], bl4[np][0], bl4[np][1]);
                    mma_bf16(sc[np * 2 + 1], qfh[ks], bl4[np][2], bl4[np][3]);
                }
#pragma unroll
                for (int np = 0; np < 4; np++) {
                    mma_bf16(sc[np * 2 + 0], qfl[ks], bh4[np][0], bh4[np][1]);
                    mma_bf16(sc[np * 2 + 1], qfl[ks], bh4[np][2], bh4[np][3]);
                }
            }

            // ---- scale + causal mask ----
            const int row0 = qbase + wq + g, row1 = row0 + 8;
#pragma unroll
            for (int nt = 0; nt < 8; nt++) {
                int kc = j * 64 + nt * 8 + 2 * tg;
                sc[nt][0] = (kc     <= row0) ? sc[nt][0] * 0.125f : -1e30f;
                sc[nt][1] = (kc + 1 <= row0) ? sc[nt][1] * 0.125f : -1e30f;
                sc[nt][2] = (kc     <= row1) ? sc[nt][2] * 0.125f : -1e30f;
                sc[nt][3] = (kc + 1 <= row1) ? sc[nt][3] * 0.125f : -1e30f;
            }

            // ---- online softmax ----
            float rm0 = -1e30f, rm1 = -1e30f;
#pragma unroll
            for (int nt = 0; nt < 8; nt++) {
                rm0 = fmaxf(rm0, fmaxf(sc[nt][0], sc[nt][1]));
                rm1 = fmaxf(rm1, fmaxf(sc[nt][2], sc[nt][3]));
            }
            rm0 = fmaxf(rm0, __shfl_xor_sync(0xffffffffu, rm0, 1));
            rm0 = fmaxf(rm0, __shfl_xor_sync(0xffffffffu, rm0, 2));
            rm1 = fmaxf(rm1, __shfl_xor_sync(0xffffffffu, rm1, 1));
            rm1 = fmaxf(rm1, __shfl_xor_sync(0xffffffffu, rm1, 2));
            float mn0 = fmaxf(m0, rm0), mn1 = fmaxf(m1, rm1);
            float al0 = __expf(m0 - mn0), al1 = __expf(m1 - mn1);
            m0 = mn0; m1 = mn1;
            float rs0 = 0.f, rs1 = 0.f;
#pragma unroll
            for (int nt = 0; nt < 8; nt++) {
                sc[nt][0] = __expf(sc[nt][0] - mn0);
                sc[nt][1] = __expf(sc[nt][1] - mn0);
                sc[nt][2] = __expf(sc[nt][2] - mn1);
                sc[nt][3] = __expf(sc[nt][3] - mn1);
                rs0 += sc[nt][0] + sc[nt][1];
                rs1 += sc[nt][2] + sc[nt][3];
            }
            rs0 += __shfl_xor_sync(0xffffffffu, rs0, 1);
            rs0 += __shfl_xor_sync(0xffffffffu, rs0, 2);
            rs1 += __shfl_xor_sync(0xffffffffu, rs1, 1);
            rs1 += __shfl_xor_sync(0xffffffffu, rs1, 2);
            l0 = l0 * al0 + rs0;
            l1 = l1 * al1 + rs1;
#pragma unroll
            for (int nt = 0; nt < 8; nt++) {
                oacc[nt][0] *= al0; oacc[nt][1] *= al0;
                oacc[nt][2] *= al1; oacc[nt][3] *= al1;
            }

            // ---- O += P @ V, term-major issue ----
#pragma unroll
            for (int ks = 0; ks < 4; ks++) {
                uint32_t pah[4], pal[4];
                split2(sc[2 * ks][0],     sc[2 * ks][1],     pah[0], pal[0]);
                split2(sc[2 * ks][2],     sc[2 * ks][3],     pah[1], pal[1]);
                split2(sc[2 * ks + 1][0], sc[2 * ks + 1][1], pah[2], pal[2]);
                split2(sc[2 * ks + 1][2], sc[2 * ks + 1][3], pah[3], pal[3]);
                uint32_t vbase = (uint32_t)(ks * 16 + vRow) * AB_ROWB + vCol;
                uint32_t vh4[4][4], vl4[4][4];
#pragma unroll
                for (int ng = 0; ng < 4; ng++) {
                    ldsm_x4_t(vh4[ng], sVH + vbase + ng * 32);
                    ldsm_x4_t(vl4[ng], sVL + vbase + ng * 32);
                }
#pragma unroll
                for (int ng = 0; ng < 4; ng++) {
                    mma_bf16(oacc[2 * ng],     pah, vh4[ng][0], vh4[ng][1]);
                    mma_bf16(oacc[2 * ng + 1], pah, vh4[ng][2], vh4[ng][3]);
                }
#pragma unroll
                for (int ng = 0; ng < 4; ng++) {
                    mma_bf16(oacc[2 * ng],     pah, vl4[ng][0], vl4[ng][1]);
                    mma_bf16(oacc[2 * ng + 1], pah, vl4[ng][2], vl4[ng][3]);
                }
#pragma unroll
                for (int ng = 0; ng < 4; ng++) {
                    mma_bf16(oacc[2 * ng],     pal, vh4[ng][0], vh4[ng][1]);
                    mma_bf16(oacc[2 * ng + 1], pal, vh4[ng][2], vh4[ng][3]);
                }
            }
        }
        __syncthreads();
    }

    // ---- epilogue: write hi/lo bf16 directly ----
    const float inv0 = 1.f / l0, inv1 = 1.f / l1;
    const size_t row0g = (size_t)(b * SEQ + qbase + wq + g);
#pragma unroll
    for (int nt = 0; nt < 8; nt++) {
        int col = hc + nt * 8 + 2 * tg;
        uint32_t hi, lo;
        split2(oacc[nt][0] * inv0, oacc[nt][1] * inv0, hi, lo);
        *reinterpret_cast<uint32_t*>(aoh + row0g * DIM + col) = hi;
        *reinterpret_cast<uint32_t*>(aol + row0g * DIM + col) = lo;
        split2(oacc[nt][2] * inv1, oacc[nt][3] * inv1, hi, lo);
        *reinterpret_cast<uint32_t*>(aoh + (row0g + 8) * DIM + col) = hi;
        *reinterpret_cast<uint32_t*>(aol + (row0g + 8) * DIM + col) = lo;
    }
}

// ---------------------------------------------------------------------------
extern "C" void kernel_launch(void* const* d_in, const int* in_sizes, int n_in,
                              void* d_out, int out_size)
{
    (void)in_sizes; (void)n_in; (void)out_size;
    const float* Q  = (const float*)d_in[0];
    const float* K  = (const float*)d_in[1];
    const float* V  = (const float*)d_in[2];
    const float* Wq = (const float*)d_in[4];
    const float* bq = (const float*)d_in[5];
    const float* Wk = (const float*)d_in[6];
    const float* bk = (const float*)d_in[7];
    const float* Wv = (const float*)d_in[8];
    const float* bv = (const float*)d_in[9];
    const float* Wo = (const float*)d_in[10];
    const float* bo = (const float*)d_in[11];

    __nv_bfloat16 *inh, *inl, *pwh, *pwl, *oh, *ol, *aoh, *aol;
    cudaGetSymbolAddress((void**)&inh, g_inh);
    cudaGetSymbolAddress((void**)&inl, g_inl);
    cudaGetSymbolAddress((void**)&pwh, g_pwh);
    cudaGetSymbolAddress((void**)&pwl, g_pwl);
    cudaGetSymbolAddress((void**)&oh,  g_oh);
    cudaGetSymbolAddress((void**)&ol,  g_ol);
    cudaGetSymbolAddress((void**)&aoh, g_aoh);
    cudaGetSymbolAddress((void**)&aol, g_aol);

    cudaFuncSetAttribute(gemm_mma,
                         cudaFuncAttributeMaxDynamicSharedMemorySize, GEMM_SMEM);
    cudaFuncSetAttribute(attn_mma,
                         cudaFuncAttributeMaxDynamicSharedMemorySize, ATTN_SMEM);

    // 1) split inputs (Q,K,V) and weights (Wq,Wk,Wv,Wo)
    split_in3<<<dim3(ASZ / 4 / 256, 3), 256>>>(Q, K, V, inh, inl);
    split_w4<<<dim3(WSZ / 4 / 256, 4), 256>>>(Wq, Wk, Wv, Wo, pwh, pwl);

    // 2) fused QKV projections (one launch, grid.z=3), bf16 hi/lo outputs
    gemm_mma<<<dim3(8, 32, 3), 256, GEMM_SMEM>>>(
        inh, inl, pwh, pwl, bq, bk, bv, oh, ol, nullptr);

    // 3) attention (HMMA, split-bf16), bf16 hi/lo output
    attn_mma<<<dim3(SEQ / 128, NH, BATCH), 256, ATTN_SMEM>>>(
        oh, ol, oh + ASZ, ol + ASZ, oh + 2 * (size_t)ASZ, ol + 2 * (size_t)ASZ,
        aoh, aol);

    // 4) output projection -> fp32 d_out
    gemm_mma<<<dim3(8, 32, 1), 256, GEMM_SMEM>>>(
        aoh, aol, pwh + 3 * (size_t)WSZ, pwl + 3 * (size_t)WSZ,
        bo, nullptr, nullptr, nullptr, nullptr, (float*)d_out);
}